// round 5
// baseline (speedup 1.0000x reference)
#include <cuda_runtime.h>
#include <math.h>

#define N_NODES 50000
#define N_EDGES 800000
#define NHEAD 8
#define D_OUT 32
#define D_IN 256
#define NH 256            // NHEAD * D_OUT
#define E_FEAT 64
#define N_ETYPES 5
#define NEG 0.2f
#define NB 196            // ceil(N_NODES / 256)

// ---------------- scratch (device globals; no allocation allowed) ----------------
__device__ float    g_h[N_NODES * NH];          // projected node features [N,8,32]
__device__ float    g_hl[N_NODES * NHEAD];
__device__ float    g_hr[N_NODES * NHEAD];
__device__ float    g_he[N_ETYPES * NHEAD];
__device__ float    g_att[N_EDGES * NHEAD];     // logits -> ex, original edge order
__device__ float    g_attp[NHEAD * N_EDGES];    // ex in CSR-permuted SoA order
__device__ unsigned g_m[N_NODES * NHEAD];       // segment max (order-preserving uint)
__device__ float    g_denom[N_NODES * NHEAD];
__device__ int      g_counts[N_NODES];
__device__ int      g_offs[N_NODES];
__device__ int      g_cursor[N_NODES];
__device__ int      g_rows[N_EDGES];            // row[] permuted into CSR order
__device__ int      g_bsums[256];
__device__ uint2    g_Wsp[D_IN * NH];           // W pre-split into tf32 (hi, lo)

// order-preserving float<->uint map for atomicMax on floats
__device__ __forceinline__ unsigned f_enc(float f) {
    unsigned u = __float_as_uint(f);
    return (u & 0x80000000u) ? ~u : (u | 0x80000000u);
}
__device__ __forceinline__ float f_dec(unsigned k) {
    return __uint_as_float((k & 0x80000000u) ? (k ^ 0x80000000u) : ~k);
}

// ---------------- tf32 helpers ----------------
__device__ __forceinline__ unsigned cvt_tf32(float x) {
    unsigned r;
    asm("cvt.rna.tf32.f32 %0, %1;" : "=r"(r) : "f"(x));
    return r;
}
__device__ __forceinline__ void tf32_split(float x, unsigned& hi, unsigned& lo) {
    hi = cvt_tf32(x);
    lo = cvt_tf32(x - __uint_as_float(hi));
}
__device__ __forceinline__ void mma_tf32(float* d, const unsigned* a, const unsigned* b) {
    asm volatile(
        "mma.sync.aligned.m16n8k8.row.col.f32.tf32.tf32.f32 "
        "{%0,%1,%2,%3}, {%4,%5,%6,%7}, {%8,%9}, {%0,%1,%2,%3};"
        : "+f"(d[0]), "+f"(d[1]), "+f"(d[2]), "+f"(d[3])
        : "r"(a[0]), "r"(a[1]), "r"(a[2]), "r"(a[3]), "r"(b[0]), "r"(b[1]));
}

// ---------------- init (+ fused he: per-etype attention dots) ----------------
__global__ void k_init(const float* __restrict__ emb, const float* __restrict__ We,
                       const float* __restrict__ a_e) {
    int i = blockIdx.x * blockDim.x + threadIdx.x;
    if (i < N_NODES) g_counts[i] = 0;
    if (i < N_NODES * NHEAD) { g_m[i] = 0u; g_denom[i] = 0.f; }
    if (blockIdx.x < N_ETYPES * NHEAD) {
        int t = blockIdx.x >> 3, hd = blockIdx.x & 7;
        __shared__ float r2[2];
        float s = 0.f;
        if (threadIdx.x < 64) {
            int f = threadIdx.x;
            float ev = 0.f;
#pragma unroll 8
            for (int k = 0; k < E_FEAT; k++)
                ev += emb[t * E_FEAT + k] * We[k * (E_FEAT * NHEAD) + hd * E_FEAT + f];
            s = ev * a_e[hd * E_FEAT + f];
#pragma unroll
            for (int o = 16; o >= 1; o >>= 1) s += __shfl_xor_sync(0xffffffffu, s, o);
            if ((threadIdx.x & 31) == 0) r2[threadIdx.x >> 5] = s;
        }
        __syncthreads();
        if (threadIdx.x == 0) g_he[t * NHEAD + hd] = r2[0] + r2[1];
    }
}

// ---------------- pre-split W into tf32 hi/lo ----------------
__global__ void k_wsplit(const float* __restrict__ W) {
    int i = blockIdx.x * blockDim.x + threadIdx.x;
    if (i < D_IN * NH) {
        unsigned hi, lo;
        tf32_split(W[i], hi, lo);
        g_Wsp[i] = make_uint2(hi, lo);
    }
}

// ---------------- GEMM: h = x @ W via 3xTF32 tensor cores + fused hl/hr epilogue ----
// block = 256 threads, 8 warps as 4(m) x 2(n): tile 128m x 256n; warp tile 32m x 128n
__global__ __launch_bounds__(256, 1) void k_gemm_tc(const float* __restrict__ X,
                                                    const float* __restrict__ a_l,
                                                    const float* __restrict__ a_r) {
    __shared__ float Xs[8][132];
    int warp = threadIdx.x >> 5, lane = threadIdx.x & 31;
    int gid = lane >> 2, tig = lane & 3;
    int wm = (warp >> 1) * 32;
    int wn = (warp & 1) * 128;
    int m0 = blockIdx.x * 128;

    float acc[2][16][4];
#pragma unroll
    for (int mt = 0; mt < 2; mt++)
#pragma unroll
        for (int nt = 0; nt < 16; nt++)
#pragma unroll
            for (int c = 0; c < 4; c++) acc[mt][nt][c] = 0.f;

    int srow = threadIdx.x >> 1;             // 0..127
    int skq = (threadIdx.x & 1) * 4;         // 0 or 4
    bool srow_ok = (m0 + srow) < N_NODES;
    const float* xp = X + (size_t)(m0 + srow) * D_IN + skq;

    for (int k0 = 0; k0 < D_IN; k0 += 8) {
        float4 v = make_float4(0.f, 0.f, 0.f, 0.f);
        if (srow_ok) v = *(const float4*)(xp + k0);
        Xs[skq + 0][srow] = v.x;
        Xs[skq + 1][srow] = v.y;
        Xs[skq + 2][srow] = v.z;
        Xs[skq + 3][srow] = v.w;
        __syncthreads();

        unsigned ah[2][4], al[2][4];
#pragma unroll
        for (int mt = 0; mt < 2; mt++) {
            int r = wm + mt * 16 + gid;
            tf32_split(Xs[tig][r],      ah[mt][0], al[mt][0]);
            tf32_split(Xs[tig][r + 8],  ah[mt][1], al[mt][1]);
            tf32_split(Xs[tig + 4][r],      ah[mt][2], al[mt][2]);
            tf32_split(Xs[tig + 4][r + 8],  ah[mt][3], al[mt][3]);
        }
#pragma unroll
        for (int nt = 0; nt < 16; nt++) {
            int c = wn + nt * 8 + gid;
            uint2 b0 = g_Wsp[(size_t)(k0 + tig) * NH + c];
            uint2 b1 = g_Wsp[(size_t)(k0 + tig + 4) * NH + c];
            unsigned bh[2] = {b0.x, b1.x};
            unsigned bl[2] = {b0.y, b1.y};
#pragma unroll
            for (int mt = 0; mt < 2; mt++) {
                mma_tf32(acc[mt][nt], ah[mt], bh);
                mma_tf32(acc[mt][nt], al[mt], bh);
                mma_tf32(acc[mt][nt], ah[mt], bl);
            }
        }
        __syncthreads();
    }

    // store h: c0,c1 -> row gid cols 2tig,2tig+1; c2,c3 -> row gid+8
#pragma unroll
    for (int mt = 0; mt < 2; mt++) {
        int r1 = m0 + wm + mt * 16 + gid;
        int r2 = r1 + 8;
#pragma unroll
        for (int nt = 0; nt < 16; nt++) {
            int c = wn + nt * 8 + 2 * tig;
            if (r1 < N_NODES)
                *(float2*)&g_h[(size_t)r1 * NH + c] = make_float2(acc[mt][nt][0], acc[mt][nt][1]);
            if (r2 < N_NODES)
                *(float2*)&g_h[(size_t)r2 * NH + c] = make_float2(acc[mt][nt][2], acc[mt][nt][3]);
        }
    }

    // fused hl/hr epilogue: warp covers rows wm..wm+31, heads wn/32 .. wn/32+3
#pragma unroll
    for (int hl_ = 0; hl_ < 4; hl_++) {
        int head = (wn >> 5) + hl_;
#pragma unroll
        for (int mt = 0; mt < 2; mt++) {
            float pl1 = 0.f, pr1 = 0.f, pl2 = 0.f, pr2 = 0.f;
#pragma unroll
            for (int q = 0; q < 4; q++) {
                int nt = hl_ * 4 + q;
                int d = q * 8 + 2 * tig;             // dim within head (0..31)
                float al0 = __ldg(a_l + head * D_OUT + d);
                float al1 = __ldg(a_l + head * D_OUT + d + 1);
                float ar0 = __ldg(a_r + head * D_OUT + d);
                float ar1 = __ldg(a_r + head * D_OUT + d + 1);
                pl1 += acc[mt][nt][0] * al0 + acc[mt][nt][1] * al1;
                pr1 += acc[mt][nt][0] * ar0 + acc[mt][nt][1] * ar1;
                pl2 += acc[mt][nt][2] * al0 + acc[mt][nt][3] * al1;
                pr2 += acc[mt][nt][2] * ar0 + acc[mt][nt][3] * ar1;
            }
#pragma unroll
            for (int o = 1; o <= 2; o <<= 1) {
                pl1 += __shfl_xor_sync(0xffffffffu, pl1, o);
                pr1 += __shfl_xor_sync(0xffffffffu, pr1, o);
                pl2 += __shfl_xor_sync(0xffffffffu, pl2, o);
                pr2 += __shfl_xor_sync(0xffffffffu, pr2, o);
            }
            if (tig == 0) {
                int r1 = m0 + wm + mt * 16 + gid;
                int r2 = r1 + 8;
                if (r1 < N_NODES) { g_hl[r1 * NHEAD + head] = pl1; g_hr[r1 * NHEAD + head] = pr1; }
                if (r2 < N_NODES) { g_hl[r2 * NHEAD + head] = pl2; g_hr[r2 * NHEAD + head] = pr2; }
            }
        }
    }
}

// ---------------- per-edge logits + segment max + histogram (fused) ----------------
__global__ void k_logits(const int* __restrict__ row, const int* __restrict__ col,
                         const int* __restrict__ et) {
    int e = blockIdx.x * blockDim.x + threadIdx.x;
    if (e >= N_EDGES) return;
    int rr = row[e], cc = col[e], tt = et[e];
    atomicAdd(&g_counts[cc], 1);
    const float4* hl4 = (const float4*)(g_hl + rr * NHEAD);
    const float4* hr4 = (const float4*)(g_hr + cc * NHEAD);
    const float4* he4 = (const float4*)(g_he + tt * NHEAD);
    float v[8];
#pragma unroll
    for (int q = 0; q < 2; q++) {
        float4 a = hl4[q], b = hr4[q], c = he4[q];
        float s;
        s = a.x + b.x + c.x; v[q * 4 + 0] = s > 0.f ? s : NEG * s;
        s = a.y + b.y + c.y; v[q * 4 + 1] = s > 0.f ? s : NEG * s;
        s = a.z + b.z + c.z; v[q * 4 + 2] = s > 0.f ? s : NEG * s;
        s = a.w + b.w + c.w; v[q * 4 + 3] = s > 0.f ? s : NEG * s;
    }
    *(float4*)(g_att + (size_t)e * 8 + 0) = make_float4(v[0], v[1], v[2], v[3]);
    *(float4*)(g_att + (size_t)e * 8 + 4) = make_float4(v[4], v[5], v[6], v[7]);
    unsigned* mp = g_m + cc * NHEAD;
#pragma unroll
    for (int i = 0; i < 8; i++) atomicMax(mp + i, f_enc(v[i]));
}

// ---------------- scans (CSR offsets over col histogram) ----------------
__global__ void k_scanA() {
    int i = blockIdx.x * 256 + threadIdx.x;
    int v = (i < N_NODES) ? g_counts[i] : 0;
    int x = v;
    int lane = threadIdx.x & 31, wid = threadIdx.x >> 5;
#pragma unroll
    for (int o = 1; o < 32; o <<= 1) {
        int y = __shfl_up_sync(0xffffffffu, x, o);
        if (lane >= o) x += y;
    }
    __shared__ int ws[8];
    if (lane == 31) ws[wid] = x;
    __syncthreads();
    if (threadIdx.x == 0) {
        int s = 0;
        for (int w = 0; w < 8; w++) { int t = ws[w]; ws[w] = s; s += t; }
    }
    __syncthreads();
    int excl = x - v + ws[wid];
    if (i < N_NODES) g_offs[i] = excl;
    if (threadIdx.x == 255) g_bsums[blockIdx.x] = excl + v;
}

__global__ void k_scanB() {
    int i = threadIdx.x;
    int v = (i < NB) ? g_bsums[i] : 0;
    int x = v;
    int lane = threadIdx.x & 31, wid = threadIdx.x >> 5;
#pragma unroll
    for (int o = 1; o < 32; o <<= 1) {
        int y = __shfl_up_sync(0xffffffffu, x, o);
        if (lane >= o) x += y;
    }
    __shared__ int ws[8];
    if (lane == 31) ws[wid] = x;
    __syncthreads();
    if (threadIdx.x == 0) {
        int s = 0;
        for (int w = 0; w < 8; w++) { int t = ws[w]; ws[w] = s; s += t; }
    }
    __syncthreads();
    int excl = x - v + ws[wid];
    if (i < NB) g_bsums[i] = excl;
}

__global__ void k_scanC() {
    int i = blockIdx.x * 256 + threadIdx.x;
    if (i < N_NODES) {
        int o = g_offs[i] + g_bsums[blockIdx.x];
        g_offs[i] = o;
        g_cursor[i] = o;
    }
}

// ---------------- fused: CSR scatter + exp + segment-sum (SoA permuted ex) -------
__global__ void k_scatter_exp(const int* __restrict__ row, const int* __restrict__ col) {
    int e = blockIdx.x * blockDim.x + threadIdx.x;
    if (e >= N_EDGES) return;
    int cc = col[e];
    int pos = atomicAdd(&g_cursor[cc], 1);
    g_rows[pos] = row[e];
    float* lp = g_att + (size_t)e * 8;
    const unsigned* mp = g_m + cc * NHEAD;
    float* dp = g_denom + cc * NHEAD;
#pragma unroll
    for (int i = 0; i < 8; i++) {
        float ex = expf(lp[i] - f_dec(mp[i]));
        lp[i] = ex;
        g_attp[(size_t)i * N_EDGES + pos] = ex;
        atomicAdd(dp + i, ex);
    }
}

// ---------------- attn output: ex / denom (write only to output slice) ----------------
__global__ void k_norm(const int* __restrict__ col, float* __restrict__ attn_out) {
    int e = blockIdx.x * blockDim.x + threadIdx.x;
    if (e >= N_EDGES) return;
    int cc = col[e];
    float4 e0 = *(const float4*)(g_att + (size_t)e * 8 + 0);
    float4 e1 = *(const float4*)(g_att + (size_t)e * 8 + 4);
    const float4* d4 = (const float4*)(g_denom + cc * NHEAD);
    float4 d0 = d4[0], d1 = d4[1];
    float4 a0 = make_float4(e0.x / d0.x, e0.y / d0.y, e0.z / d0.z, e0.w / d0.w);
    float4 a1 = make_float4(e1.x / d1.x, e1.y / d1.y, e1.z / d1.z, e1.w / d1.w);
    *(float4*)(attn_out + (size_t)e * 8 + 0) = a0;
    *(float4*)(attn_out + (size_t)e * 8 + 4) = a1;
}

// ---------------- CSR aggregation: out[n] = (1/denom) * sum_e ex * h[row] ----------------
__global__ __launch_bounds__(256) void k_agg(float* __restrict__ out) {
    int n = blockIdx.x;
    int head = threadIdx.x >> 5;
    int lane = threadIdx.x & 31;
    int start = g_offs[n];
    int cnt = g_counts[n];
    float acc = 0.f;
    for (int base = 0; base < cnt; base += 32) {
        int m = min(cnt - base, 32);
        float a = 0.f;
        int r = 0;
        if (lane < m) {
            a = g_attp[(size_t)head * N_EDGES + start + base + lane];  // ex, CSR order
            r = g_rows[start + base + lane];
        }
        for (int jj = 0; jj < m; jj++) {
            float aj = __shfl_sync(0xffffffffu, a, jj);
            int rj = __shfl_sync(0xffffffffu, r, jj);
            acc = fmaf(aj, g_h[(size_t)rj * NH + head * D_OUT + lane], acc);
        }
    }
    float scale = (cnt > 0) ? (1.f / g_denom[n * NHEAD + head]) : 0.f;
    out[(size_t)n * NH + head * D_OUT + lane] = acc * scale;
}

// ---------------- launch ----------------
extern "C" void kernel_launch(void* const* d_in, const int* in_sizes, int n_in,
                              void* d_out, int out_size) {
    const float* x   = (const float*)d_in[0];
    const float* W   = (const float*)d_in[1];
    const float* We  = (const float*)d_in[2];
    const float* emb = (const float*)d_in[3];
    const float* a_l = (const float*)d_in[4];
    const float* a_r = (const float*)d_in[5];
    const float* a_e = (const float*)d_in[6];
    const int* row = (const int*)d_in[7];
    const int* col = (const int*)d_in[8];
    const int* et  = (const int*)d_in[9];
    float* out = (float*)d_out;
    float* attn_out = (out_size >= N_NODES * NH + N_EDGES * NHEAD)
                          ? (out + (size_t)N_NODES * NH)
                          : nullptr;

    const int EB = (N_EDGES + 255) / 256;

    k_init<<<(N_NODES * NHEAD + 255) / 256, 256>>>(emb, We, a_e);
    k_wsplit<<<(D_IN * NH + 255) / 256, 256>>>(W);

    k_gemm_tc<<<(N_NODES + 127) / 128, 256>>>(x, a_l, a_r);

    k_logits<<<EB, 256>>>(row, col, et);
    k_scanA<<<NB, 256>>>();
    k_scanB<<<1, 256>>>();
    k_scanC<<<NB, 256>>>();
    k_scatter_exp<<<EB, 256>>>(row, col);

    if (attn_out) k_norm<<<EB, 256>>>(col, attn_out);
    k_agg<<<N_NODES, 256>>>(out);
}

// round 6
// speedup vs baseline: 1.1169x; 1.1169x over previous
#include <cuda_runtime.h>
#include <math.h>

#define N_NODES 50000
#define N_EDGES 800000
#define NHEAD 8
#define D_OUT 32
#define D_IN 256
#define NH 256            // NHEAD * D_OUT
#define E_FEAT 64
#define N_ETYPES 5
#define NEG 0.2f
#define NB 196            // ceil(N_NODES / 256)

// ---------------- scratch (device globals; no allocation allowed) ----------------
__device__ float    g_h[N_NODES * NH];          // projected node features [N,8,32]
__device__ float    g_hl[N_NODES * NHEAD];
__device__ float    g_hr[N_NODES * NHEAD];
__device__ float    g_he[N_ETYPES * NHEAD];
__device__ float    g_att[N_EDGES * NHEAD];     // ex, original edge order (for attn out)
__device__ float    g_attp[NHEAD * N_EDGES];    // ex in CSR-permuted SoA order
__device__ float    g_denom[N_NODES * NHEAD];
__device__ int      g_counts[N_NODES];
__device__ int      g_offs[N_NODES];
__device__ int      g_cursor[N_NODES];
__device__ int      g_rows[N_EDGES];            // row[] permuted into CSR order
__device__ int      g_bsums[256];
__device__ uint2    g_Wsp[D_IN * NH];           // W pre-split into tf32 (hi, lo)

// ---------------- tf32 helpers ----------------
__device__ __forceinline__ unsigned cvt_tf32(float x) {
    unsigned r;
    asm("cvt.rna.tf32.f32 %0, %1;" : "=r"(r) : "f"(x));
    return r;
}
__device__ __forceinline__ void tf32_split(float x, unsigned& hi, unsigned& lo) {
    hi = cvt_tf32(x);
    lo = cvt_tf32(x - __uint_as_float(hi));
}
__device__ __forceinline__ void mma_tf32(float* d, const unsigned* a, const unsigned* b) {
    asm volatile(
        "mma.sync.aligned.m16n8k8.row.col.f32.tf32.tf32.f32 "
        "{%0,%1,%2,%3}, {%4,%5,%6,%7}, {%8,%9}, {%0,%1,%2,%3};"
        : "+f"(d[0]), "+f"(d[1]), "+f"(d[2]), "+f"(d[3])
        : "r"(a[0]), "r"(a[1]), "r"(a[2]), "r"(a[3]), "r"(b[0]), "r"(b[1]));
}

// ---------------- init (+ fused he: per-etype attention dots) ----------------
__global__ void k_init(const float* __restrict__ emb, const float* __restrict__ We,
                       const float* __restrict__ a_e) {
    int i = blockIdx.x * blockDim.x + threadIdx.x;
    if (i < N_NODES) g_counts[i] = 0;
    if (i < N_NODES * NHEAD) g_denom[i] = 0.f;
    if (blockIdx.x < N_ETYPES * NHEAD) {
        int t = blockIdx.x >> 3, hd = blockIdx.x & 7;
        __shared__ float r2[2];
        float s = 0.f;
        if (threadIdx.x < 64) {
            int f = threadIdx.x;
            float ev = 0.f;
#pragma unroll 8
            for (int k = 0; k < E_FEAT; k++)
                ev += emb[t * E_FEAT + k] * We[k * (E_FEAT * NHEAD) + hd * E_FEAT + f];
            s = ev * a_e[hd * E_FEAT + f];
#pragma unroll
            for (int o = 16; o >= 1; o >>= 1) s += __shfl_xor_sync(0xffffffffu, s, o);
            if ((threadIdx.x & 31) == 0) r2[threadIdx.x >> 5] = s;
        }
        __syncthreads();
        if (threadIdx.x == 0) g_he[t * NHEAD + hd] = r2[0] + r2[1];
    }
}

// ---------------- pre-split W into tf32 hi/lo ----------------
__global__ void k_wsplit(const float* __restrict__ W) {
    int i = blockIdx.x * blockDim.x + threadIdx.x;
    if (i < D_IN * NH) {
        unsigned hi, lo;
        tf32_split(W[i], hi, lo);
        g_Wsp[i] = make_uint2(hi, lo);
    }
}

// ---------------- GEMM: h = x @ W via 3xTF32 (R4 shape + smem X + pre-split W) ------
// block = 256 threads, 8 warps 4(m) x 2(n): tile 128m x 128n; warp tile 32m x 64n
__global__ __launch_bounds__(256, 2) void k_gemm_tc(const float* __restrict__ X) {
    __shared__ float Xs[8][136];      // stride 136: conflict-free frag reads
    int warp = threadIdx.x >> 5, lane = threadIdx.x & 31;
    int gid = lane >> 2, tig = lane & 3;
    int wm = (warp >> 1) * 32;
    int wn = (warp & 1) * 64;
    int m0 = blockIdx.y * 128;
    int n0 = blockIdx.x * 128;

    float acc[2][8][4];
#pragma unroll
    for (int mt = 0; mt < 2; mt++)
#pragma unroll
        for (int nt = 0; nt < 8; nt++)
#pragma unroll
            for (int c = 0; c < 4; c++) acc[mt][nt][c] = 0.f;

    int srow = threadIdx.x >> 1;             // 0..127
    int skq = (threadIdx.x & 1) * 4;         // 0 or 4
    bool srow_ok = (m0 + srow) < N_NODES;
    const float* xp = X + (size_t)(m0 + srow) * D_IN + skq;

    for (int k0 = 0; k0 < D_IN; k0 += 8) {
        float4 v = make_float4(0.f, 0.f, 0.f, 0.f);
        if (srow_ok) v = *(const float4*)(xp + k0);
        Xs[skq + 0][srow] = v.x;
        Xs[skq + 1][srow] = v.y;
        Xs[skq + 2][srow] = v.z;
        Xs[skq + 3][srow] = v.w;
        __syncthreads();

        unsigned ah[2][4], al[2][4];
#pragma unroll
        for (int mt = 0; mt < 2; mt++) {
            int r = wm + mt * 16 + gid;
            tf32_split(Xs[tig][r],         ah[mt][0], al[mt][0]);
            tf32_split(Xs[tig][r + 8],     ah[mt][1], al[mt][1]);
            tf32_split(Xs[tig + 4][r],     ah[mt][2], al[mt][2]);
            tf32_split(Xs[tig + 4][r + 8], ah[mt][3], al[mt][3]);
        }
#pragma unroll
        for (int nt = 0; nt < 8; nt++) {
            int c = n0 + wn + nt * 8 + gid;
            uint2 b0 = g_Wsp[(size_t)(k0 + tig) * NH + c];
            uint2 b1 = g_Wsp[(size_t)(k0 + tig + 4) * NH + c];
            unsigned bh[2] = {b0.x, b1.x};
            unsigned bl[2] = {b0.y, b1.y};
#pragma unroll
            for (int mt = 0; mt < 2; mt++) {
                mma_tf32(acc[mt][nt], ah[mt], bh);
                mma_tf32(acc[mt][nt], al[mt], bh);
                mma_tf32(acc[mt][nt], ah[mt], bl);
            }
        }
        __syncthreads();
    }

#pragma unroll
    for (int mt = 0; mt < 2; mt++) {
        int r1 = m0 + wm + mt * 16 + gid;
        int r2 = r1 + 8;
#pragma unroll
        for (int nt = 0; nt < 8; nt++) {
            int c = n0 + wn + nt * 8 + 2 * tig;
            if (r1 < N_NODES)
                *(float2*)&g_h[(size_t)r1 * NH + c] = make_float2(acc[mt][nt][0], acc[mt][nt][1]);
            if (r2 < N_NODES)
                *(float2*)&g_h[(size_t)r2 * NH + c] = make_float2(acc[mt][nt][2], acc[mt][nt][3]);
        }
    }
}

// ---------------- hl / hr: per-node attention dots ----------------
__global__ void k_hlhr(const float* __restrict__ a_l, const float* __restrict__ a_r) {
    int warp = threadIdx.x >> 5;
    int lane = threadIdx.x & 31;
    int n = blockIdx.x * 8 + warp;
    if (n >= N_NODES) return;
#pragma unroll
    for (int it = 0; it < 2; it++) {
        int off = it * 128 + lane * 4;
        int hd = off >> 5;
        int d0 = off & 31;
        float4 v  = *(const float4*)(g_h + (size_t)n * NH + off);
        float4 al = *(const float4*)(a_l + hd * D_OUT + d0);
        float4 ar = *(const float4*)(a_r + hd * D_OUT + d0);
        float pl = v.x * al.x + v.y * al.y + v.z * al.z + v.w * al.w;
        float pr = v.x * ar.x + v.y * ar.y + v.z * ar.z + v.w * ar.w;
#pragma unroll
        for (int o = 4; o >= 1; o >>= 1) {
            pl += __shfl_xor_sync(0xffffffffu, pl, o);
            pr += __shfl_xor_sync(0xffffffffu, pr, o);
        }
        if ((lane & 7) == 0) {
            g_hl[n * NHEAD + hd] = pl;
            g_hr[n * NHEAD + hd] = pr;
        }
    }
}

// ---------------- histogram over col ----------------
__global__ void k_hist(const int* __restrict__ col) {
    int e = blockIdx.x * blockDim.x + threadIdx.x;
    if (e < N_EDGES) atomicAdd(&g_counts[col[e]], 1);
}

// ---------------- scans (CSR offsets over col histogram) ----------------
__global__ void k_scanA() {
    int i = blockIdx.x * 256 + threadIdx.x;
    int v = (i < N_NODES) ? g_counts[i] : 0;
    int x = v;
    int lane = threadIdx.x & 31, wid = threadIdx.x >> 5;
#pragma unroll
    for (int o = 1; o < 32; o <<= 1) {
        int y = __shfl_up_sync(0xffffffffu, x, o);
        if (lane >= o) x += y;
    }
    __shared__ int ws[8];
    if (lane == 31) ws[wid] = x;
    __syncthreads();
    if (threadIdx.x == 0) {
        int s = 0;
        for (int w = 0; w < 8; w++) { int t = ws[w]; ws[w] = s; s += t; }
    }
    __syncthreads();
    int excl = x - v + ws[wid];
    if (i < N_NODES) g_offs[i] = excl;
    if (threadIdx.x == 255) g_bsums[blockIdx.x] = excl + v;
}

__global__ void k_scanB() {
    int i = threadIdx.x;
    int v = (i < NB) ? g_bsums[i] : 0;
    int x = v;
    int lane = threadIdx.x & 31, wid = threadIdx.x >> 5;
#pragma unroll
    for (int o = 1; o < 32; o <<= 1) {
        int y = __shfl_up_sync(0xffffffffu, x, o);
        if (lane >= o) x += y;
    }
    __shared__ int ws[8];
    if (lane == 31) ws[wid] = x;
    __syncthreads();
    if (threadIdx.x == 0) {
        int s = 0;
        for (int w = 0; w < 8; w++) { int t = ws[w]; ws[w] = s; s += t; }
    }
    __syncthreads();
    int excl = x - v + ws[wid];
    if (i < NB) g_bsums[i] = excl;
}

__global__ void k_scanC() {
    int i = blockIdx.x * 256 + threadIdx.x;
    if (i < N_NODES) {
        int o = g_offs[i] + g_bsums[blockIdx.x];
        g_offs[i] = o;
        g_cursor[i] = o;
    }
}

// ------- fused edge pass: logits + exp (no max needed) + CSR scatter + denom -------
__global__ void k_edge(const int* __restrict__ row, const int* __restrict__ col,
                       const int* __restrict__ et) {
    int e = blockIdx.x * blockDim.x + threadIdx.x;
    if (e >= N_EDGES) return;
    int rr = row[e], cc = col[e], tt = et[e];
    int pos = atomicAdd(&g_cursor[cc], 1);
    g_rows[pos] = rr;
    const float4* hl4 = (const float4*)(g_hl + rr * NHEAD);
    const float4* hr4 = (const float4*)(g_hr + cc * NHEAD);
    const float4* he4 = (const float4*)(g_he + tt * NHEAD);
    float v[8];
#pragma unroll
    for (int q = 0; q < 2; q++) {
        float4 a = hl4[q], b = hr4[q], c = he4[q];
        float s;
        s = a.x + b.x + c.x; s = s > 0.f ? s : NEG * s; v[q * 4 + 0] = __expf(s);
        s = a.y + b.y + c.y; s = s > 0.f ? s : NEG * s; v[q * 4 + 1] = __expf(s);
        s = a.z + b.z + c.z; s = s > 0.f ? s : NEG * s; v[q * 4 + 2] = __expf(s);
        s = a.w + b.w + c.w; s = s > 0.f ? s : NEG * s; v[q * 4 + 3] = __expf(s);
    }
    *(float4*)(g_att + (size_t)e * 8 + 0) = make_float4(v[0], v[1], v[2], v[3]);
    *(float4*)(g_att + (size_t)e * 8 + 4) = make_float4(v[4], v[5], v[6], v[7]);
    float* dp = g_denom + cc * NHEAD;
#pragma unroll
    for (int i = 0; i < 8; i++) {
        g_attp[(size_t)i * N_EDGES + pos] = v[i];
        atomicAdd(dp + i, v[i]);
    }
}

// ---------------- attn output: ex / denom ----------------
__global__ void k_norm(const int* __restrict__ col, float* __restrict__ attn_out) {
    int e = blockIdx.x * blockDim.x + threadIdx.x;
    if (e >= N_EDGES) return;
    int cc = col[e];
    float4 e0 = *(const float4*)(g_att + (size_t)e * 8 + 0);
    float4 e1 = *(const float4*)(g_att + (size_t)e * 8 + 4);
    const float4* d4 = (const float4*)(g_denom + cc * NHEAD);
    float4 d0 = d4[0], d1 = d4[1];
    float4 a0 = make_float4(e0.x / d0.x, e0.y / d0.y, e0.z / d0.z, e0.w / d0.w);
    float4 a1 = make_float4(e1.x / d1.x, e1.y / d1.y, e1.z / d1.z, e1.w / d1.w);
    *(float4*)(attn_out + (size_t)e * 8 + 0) = a0;
    *(float4*)(attn_out + (size_t)e * 8 + 4) = a1;
}

// ------- CSR aggregation with 4-way ILP: out[n] = (1/denom) * sum ex * h[row] ------
__global__ __launch_bounds__(256) void k_agg(float* __restrict__ out) {
    int n = blockIdx.x;
    int head = threadIdx.x >> 5;
    int lane = threadIdx.x & 31;
    int start = g_offs[n];
    int cnt = g_counts[n];
    float acc0 = 0.f, acc1 = 0.f, acc2 = 0.f, acc3 = 0.f;
    const float* hbase = g_h + head * D_OUT + lane;
    for (int base = 0; base < cnt; base += 32) {
        int m = min(cnt - base, 32);
        float a = 0.f;
        int r = 0;
        if (lane < m) {
            a = g_attp[(size_t)head * N_EDGES + start + base + lane];
            r = g_rows[start + base + lane];
        }
        int jj = 0;
        for (; jj + 4 <= m; jj += 4) {
            float a0 = __shfl_sync(0xffffffffu, a, jj + 0);
            float a1 = __shfl_sync(0xffffffffu, a, jj + 1);
            float a2 = __shfl_sync(0xffffffffu, a, jj + 2);
            float a3 = __shfl_sync(0xffffffffu, a, jj + 3);
            int r0 = __shfl_sync(0xffffffffu, r, jj + 0);
            int r1 = __shfl_sync(0xffffffffu, r, jj + 1);
            int r2 = __shfl_sync(0xffffffffu, r, jj + 2);
            int r3 = __shfl_sync(0xffffffffu, r, jj + 3);
            float h0 = __ldg(hbase + (size_t)r0 * NH);
            float h1 = __ldg(hbase + (size_t)r1 * NH);
            float h2 = __ldg(hbase + (size_t)r2 * NH);
            float h3 = __ldg(hbase + (size_t)r3 * NH);
            acc0 = fmaf(a0, h0, acc0);
            acc1 = fmaf(a1, h1, acc1);
            acc2 = fmaf(a2, h2, acc2);
            acc3 = fmaf(a3, h3, acc3);
        }
        for (; jj < m; jj++) {
            float aj = __shfl_sync(0xffffffffu, a, jj);
            int rj = __shfl_sync(0xffffffffu, r, jj);
            acc0 = fmaf(aj, __ldg(hbase + (size_t)rj * NH), acc0);
        }
    }
    float acc = (acc0 + acc1) + (acc2 + acc3);
    float scale = (cnt > 0) ? (1.f / g_denom[n * NHEAD + head]) : 0.f;
    out[(size_t)n * NH + head * D_OUT + lane] = acc * scale;
}

// ---------------- launch ----------------
extern "C" void kernel_launch(void* const* d_in, const int* in_sizes, int n_in,
                              void* d_out, int out_size) {
    const float* x   = (const float*)d_in[0];
    const float* W   = (const float*)d_in[1];
    const float* We  = (const float*)d_in[2];
    const float* emb = (const float*)d_in[3];
    const float* a_l = (const float*)d_in[4];
    const float* a_r = (const float*)d_in[5];
    const float* a_e = (const float*)d_in[6];
    const int* row = (const int*)d_in[7];
    const int* col = (const int*)d_in[8];
    const int* et  = (const int*)d_in[9];
    float* out = (float*)d_out;
    float* attn_out = (out_size >= N_NODES * NH + N_EDGES * NHEAD)
                          ? (out + (size_t)N_NODES * NH)
                          : nullptr;

    const int EB = (N_EDGES + 255) / 256;

    k_init<<<(N_NODES * NHEAD + 255) / 256, 256>>>(emb, We, a_e);
    k_wsplit<<<(D_IN * NH + 255) / 256, 256>>>(W);

    dim3 ggrid(2, (N_NODES + 127) / 128);
    k_gemm_tc<<<ggrid, 256>>>(x);
    k_hlhr<<<(N_NODES + 7) / 8, 256>>>(a_l, a_r);

    k_hist<<<EB, 256>>>(col);
    k_scanA<<<NB, 256>>>();
    k_scanB<<<1, 256>>>();
    k_scanC<<<NB, 256>>>();
    k_edge<<<EB, 256>>>(row, col, et);

    if (attn_out) k_norm<<<EB, 256>>>(col, attn_out);
    k_agg<<<N_NODES, 256>>>(out);
}

// round 7
// speedup vs baseline: 1.5036x; 1.3462x over previous
#include <cuda_runtime.h>
#include <math.h>

#define N_NODES 50000
#define N_EDGES 800000
#define NHEAD 8
#define D_OUT 32
#define D_IN 256
#define NH 256            // NHEAD * D_OUT
#define E_FEAT 64
#define N_ETYPES 5
#define NEG 0.2f
#define NB 196            // ceil(N_NODES / 256)

// ---------------- scratch (device globals; no allocation allowed) ----------------
__device__ float    g_h[N_NODES * NH];          // projected node features [N,8,32]
__device__ float    g_hl[N_NODES * NHEAD];
__device__ float    g_hr[N_NODES * NHEAD];
__device__ float    g_he[N_ETYPES * NHEAD];
__device__ float    g_att[N_EDGES * NHEAD];     // ex, original edge order
__device__ float    g_denom[N_NODES * NHEAD];
__device__ int      g_counts[N_NODES];
__device__ int      g_offs[N_NODES];
__device__ int      g_cursor[N_NODES];
__device__ int      g_perm[N_EDGES];            // CSR pos -> original edge id
__device__ int      g_rows[N_EDGES];            // row[] permuted into CSR order
__device__ int      g_bsums[256];
__device__ uint2    g_Wsp[D_IN * NH];           // W pre-split into tf32 (hi, lo)

// ---------------- tf32 helpers ----------------
__device__ __forceinline__ unsigned cvt_tf32(float x) {
    unsigned r;
    asm("cvt.rna.tf32.f32 %0, %1;" : "=r"(r) : "f"(x));
    return r;
}
__device__ __forceinline__ void tf32_split(float x, unsigned& hi, unsigned& lo) {
    hi = cvt_tf32(x);
    lo = cvt_tf32(x - __uint_as_float(hi));
}
__device__ __forceinline__ void mma_tf32(float* d, const unsigned* a, const unsigned* b) {
    asm volatile(
        "mma.sync.aligned.m16n8k8.row.col.f32.tf32.tf32.f32 "
        "{%0,%1,%2,%3}, {%4,%5,%6,%7}, {%8,%9}, {%0,%1,%2,%3};"
        : "+f"(d[0]), "+f"(d[1]), "+f"(d[2]), "+f"(d[3])
        : "r"(a[0]), "r"(a[1]), "r"(a[2]), "r"(a[3]), "r"(b[0]), "r"(b[1]));
}

// ---------------- init (+ fused he: per-etype attention dots) ----------------
__global__ void k_init(const float* __restrict__ emb, const float* __restrict__ We,
                       const float* __restrict__ a_e) {
    int i = blockIdx.x * blockDim.x + threadIdx.x;
    if (i < N_NODES) g_counts[i] = 0;
    if (i < N_NODES * NHEAD) g_denom[i] = 0.f;
    if (blockIdx.x < N_ETYPES * NHEAD) {
        int t = blockIdx.x >> 3, hd = blockIdx.x & 7;
        __shared__ float r2[2];
        float s = 0.f;
        if (threadIdx.x < 64) {
            int f = threadIdx.x;
            float ev = 0.f;
#pragma unroll 8
            for (int k = 0; k < E_FEAT; k++)
                ev += emb[t * E_FEAT + k] * We[k * (E_FEAT * NHEAD) + hd * E_FEAT + f];
            s = ev * a_e[hd * E_FEAT + f];
#pragma unroll
            for (int o = 16; o >= 1; o >>= 1) s += __shfl_xor_sync(0xffffffffu, s, o);
            if ((threadIdx.x & 31) == 0) r2[threadIdx.x >> 5] = s;
        }
        __syncthreads();
        if (threadIdx.x == 0) g_he[t * NHEAD + hd] = r2[0] + r2[1];
    }
}

// ---------------- pre-split W into tf32 hi/lo ----------------
__global__ void k_wsplit(const float* __restrict__ W) {
    int i = blockIdx.x * blockDim.x + threadIdx.x;
    if (i < D_IN * NH) {
        unsigned hi, lo;
        tf32_split(W[i], hi, lo);
        g_Wsp[i] = make_uint2(hi, lo);
    }
}

// ---------------- GEMM: h = x @ W via 3xTF32 (smem X + pre-split W) ------
__global__ __launch_bounds__(256, 2) void k_gemm_tc(const float* __restrict__ X) {
    __shared__ float Xs[8][136];
    int warp = threadIdx.x >> 5, lane = threadIdx.x & 31;
    int gid = lane >> 2, tig = lane & 3;
    int wm = (warp >> 1) * 32;
    int wn = (warp & 1) * 64;
    int m0 = blockIdx.y * 128;
    int n0 = blockIdx.x * 128;

    float acc[2][8][4];
#pragma unroll
    for (int mt = 0; mt < 2; mt++)
#pragma unroll
        for (int nt = 0; nt < 8; nt++)
#pragma unroll
            for (int c = 0; c < 4; c++) acc[mt][nt][c] = 0.f;

    int srow = threadIdx.x >> 1;
    int skq = (threadIdx.x & 1) * 4;
    bool srow_ok = (m0 + srow) < N_NODES;
    const float* xp = X + (size_t)(m0 + srow) * D_IN + skq;

    for (int k0 = 0; k0 < D_IN; k0 += 8) {
        float4 v = make_float4(0.f, 0.f, 0.f, 0.f);
        if (srow_ok) v = *(const float4*)(xp + k0);
        Xs[skq + 0][srow] = v.x;
        Xs[skq + 1][srow] = v.y;
        Xs[skq + 2][srow] = v.z;
        Xs[skq + 3][srow] = v.w;
        __syncthreads();

        unsigned ah[2][4], al[2][4];
#pragma unroll
        for (int mt = 0; mt < 2; mt++) {
            int r = wm + mt * 16 + gid;
            tf32_split(Xs[tig][r],         ah[mt][0], al[mt][0]);
            tf32_split(Xs[tig][r + 8],     ah[mt][1], al[mt][1]);
            tf32_split(Xs[tig + 4][r],     ah[mt][2], al[mt][2]);
            tf32_split(Xs[tig + 4][r + 8], ah[mt][3], al[mt][3]);
        }
#pragma unroll
        for (int nt = 0; nt < 8; nt++) {
            int c = n0 + wn + nt * 8 + gid;
            uint2 b0 = g_Wsp[(size_t)(k0 + tig) * NH + c];
            uint2 b1 = g_Wsp[(size_t)(k0 + tig + 4) * NH + c];
            unsigned bh[2] = {b0.x, b1.x};
            unsigned bl[2] = {b0.y, b1.y};
#pragma unroll
            for (int mt = 0; mt < 2; mt++) {
                mma_tf32(acc[mt][nt], ah[mt], bh);
                mma_tf32(acc[mt][nt], al[mt], bh);
                mma_tf32(acc[mt][nt], ah[mt], bl);
            }
        }
        __syncthreads();
    }

#pragma unroll
    for (int mt = 0; mt < 2; mt++) {
        int r1 = m0 + wm + mt * 16 + gid;
        int r2 = r1 + 8;
#pragma unroll
        for (int nt = 0; nt < 8; nt++) {
            int c = n0 + wn + nt * 8 + 2 * tig;
            if (r1 < N_NODES)
                *(float2*)&g_h[(size_t)r1 * NH + c] = make_float2(acc[mt][nt][0], acc[mt][nt][1]);
            if (r2 < N_NODES)
                *(float2*)&g_h[(size_t)r2 * NH + c] = make_float2(acc[mt][nt][2], acc[mt][nt][3]);
        }
    }
}

// ---------------- hl / hr: per-node attention dots ----------------
__global__ void k_hlhr(const float* __restrict__ a_l, const float* __restrict__ a_r) {
    int warp = threadIdx.x >> 5;
    int lane = threadIdx.x & 31;
    int n = blockIdx.x * 8 + warp;
    if (n >= N_NODES) return;
#pragma unroll
    for (int it = 0; it < 2; it++) {
        int off = it * 128 + lane * 4;
        int hd = off >> 5;
        int d0 = off & 31;
        float4 v  = *(const float4*)(g_h + (size_t)n * NH + off);
        float4 al = *(const float4*)(a_l + hd * D_OUT + d0);
        float4 ar = *(const float4*)(a_r + hd * D_OUT + d0);
        float pl = v.x * al.x + v.y * al.y + v.z * al.z + v.w * al.w;
        float pr = v.x * ar.x + v.y * ar.y + v.z * ar.z + v.w * ar.w;
#pragma unroll
        for (int o = 4; o >= 1; o >>= 1) {
            pl += __shfl_xor_sync(0xffffffffu, pl, o);
            pr += __shfl_xor_sync(0xffffffffu, pr, o);
        }
        if ((lane & 7) == 0) {
            g_hl[n * NHEAD + hd] = pl;
            g_hr[n * NHEAD + hd] = pr;
        }
    }
}

// ---------------- histogram over col ----------------
__global__ void k_hist(const int* __restrict__ col) {
    int e = blockIdx.x * blockDim.x + threadIdx.x;
    if (e < N_EDGES) atomicAdd(&g_counts[col[e]], 1);
}

// ---------------- scans (CSR offsets over col histogram) ----------------
__global__ void k_scanA() {
    int i = blockIdx.x * 256 + threadIdx.x;
    int v = (i < N_NODES) ? g_counts[i] : 0;
    int x = v;
    int lane = threadIdx.x & 31, wid = threadIdx.x >> 5;
#pragma unroll
    for (int o = 1; o < 32; o <<= 1) {
        int y = __shfl_up_sync(0xffffffffu, x, o);
        if (lane >= o) x += y;
    }
    __shared__ int ws[8];
    if (lane == 31) ws[wid] = x;
    __syncthreads();
    if (threadIdx.x == 0) {
        int s = 0;
        for (int w = 0; w < 8; w++) { int t = ws[w]; ws[w] = s; s += t; }
    }
    __syncthreads();
    int excl = x - v + ws[wid];
    if (i < N_NODES) g_offs[i] = excl;
    if (threadIdx.x == 255) g_bsums[blockIdx.x] = excl + v;
}

__global__ void k_scanB() {
    int i = threadIdx.x;
    int v = (i < NB) ? g_bsums[i] : 0;
    int x = v;
    int lane = threadIdx.x & 31, wid = threadIdx.x >> 5;
#pragma unroll
    for (int o = 1; o < 32; o <<= 1) {
        int y = __shfl_up_sync(0xffffffffu, x, o);
        if (lane >= o) x += y;
    }
    __shared__ int ws[8];
    if (lane == 31) ws[wid] = x;
    __syncthreads();
    if (threadIdx.x == 0) {
        int s = 0;
        for (int w = 0; w < 8; w++) { int t = ws[w]; ws[w] = s; s += t; }
    }
    __syncthreads();
    int excl = x - v + ws[wid];
    if (i < NB) g_bsums[i] = excl;
}

__global__ void k_scanC() {
    int i = blockIdx.x * 256 + threadIdx.x;
    if (i < N_NODES) {
        int o = g_offs[i] + g_bsums[blockIdx.x];
        g_offs[i] = o;
        g_cursor[i] = o;
    }
}

// ------- fused edge pass: logits + exp (no max needed) + CSR scatter + denom -------
__global__ void k_edge(const int* __restrict__ row, const int* __restrict__ col,
                       const int* __restrict__ et) {
    int e = blockIdx.x * blockDim.x + threadIdx.x;
    if (e >= N_EDGES) return;
    int rr = row[e], cc = col[e], tt = et[e];
    int pos = atomicAdd(&g_cursor[cc], 1);
    g_perm[pos] = e;
    g_rows[pos] = rr;
    const float4* hl4 = (const float4*)(g_hl + rr * NHEAD);
    const float4* hr4 = (const float4*)(g_hr + cc * NHEAD);
    const float4* he4 = (const float4*)(g_he + tt * NHEAD);
    float v[8];
#pragma unroll
    for (int q = 0; q < 2; q++) {
        float4 a = hl4[q], b = hr4[q], c = he4[q];
        float s;
        s = a.x + b.x + c.x; s = s > 0.f ? s : NEG * s; v[q * 4 + 0] = __expf(s);
        s = a.y + b.y + c.y; s = s > 0.f ? s : NEG * s; v[q * 4 + 1] = __expf(s);
        s = a.z + b.z + c.z; s = s > 0.f ? s : NEG * s; v[q * 4 + 2] = __expf(s);
        s = a.w + b.w + c.w; s = s > 0.f ? s : NEG * s; v[q * 4 + 3] = __expf(s);
    }
    *(float4*)(g_att + (size_t)e * 8 + 0) = make_float4(v[0], v[1], v[2], v[3]);
    *(float4*)(g_att + (size_t)e * 8 + 4) = make_float4(v[4], v[5], v[6], v[7]);
    float* dp = g_denom + cc * NHEAD;
#pragma unroll
    for (int i = 0; i < 8; i++) atomicAdd(dp + i, v[i]);
}

// ---------------- attn output: ex / denom ----------------
__global__ void k_norm(const int* __restrict__ col, float* __restrict__ attn_out) {
    int e = blockIdx.x * blockDim.x + threadIdx.x;
    if (e >= N_EDGES) return;
    int cc = col[e];
    float4 e0 = *(const float4*)(g_att + (size_t)e * 8 + 0);
    float4 e1 = *(const float4*)(g_att + (size_t)e * 8 + 4);
    const float4* d4 = (const float4*)(g_denom + cc * NHEAD);
    float4 d0 = d4[0], d1 = d4[1];
    float4 a0 = make_float4(e0.x / d0.x, e0.y / d0.y, e0.z / d0.z, e0.w / d0.w);
    float4 a1 = make_float4(e1.x / d1.x, e1.y / d1.y, e1.z / d1.z, e1.w / d1.w);
    *(float4*)(attn_out + (size_t)e * 8 + 0) = a0;
    *(float4*)(attn_out + (size_t)e * 8 + 4) = a1;
}

// ------- CSR aggregation: warp per node, all heads; lane owns 8 dims -------
// out[n, l*8 .. l*8+7] = (1/denom[head]) * sum_e ex(e,head) * h[row_e, l*8..]
__global__ __launch_bounds__(256) void k_agg(float* __restrict__ out) {
    int n = blockIdx.x * 8 + (threadIdx.x >> 5);
    if (n >= N_NODES) return;
    int lane = threadIdx.x & 31;
    int head = lane >> 2;               // 8 floats per lane -> head = lane/4
    int start = g_offs[n];
    int cnt = g_counts[n];

    float4 accA0 = make_float4(0.f, 0.f, 0.f, 0.f), accA1 = accA0;
    float4 accB0 = accA0, accB1 = accA0;

    for (int base = 0; base < cnt; base += 32) {
        int m = min(cnt - base, 32);
        int pm = 0, rr = 0;
        if (lane < m) {
            pm = g_perm[start + base + lane];
            rr = g_rows[start + base + lane];
        }
        int j = 0;
        for (; j + 2 <= m; j += 2) {
            int p0 = __shfl_sync(0xffffffffu, pm, j);
            int r0 = __shfl_sync(0xffffffffu, rr, j);
            int p1 = __shfl_sync(0xffffffffu, pm, j + 1);
            int r1 = __shfl_sync(0xffffffffu, rr, j + 1);
            float a0 = __ldg(g_att + (size_t)p0 * 8 + head);
            float a1 = __ldg(g_att + (size_t)p1 * 8 + head);
            const float4* hp0 = (const float4*)(g_h + (size_t)r0 * NH + lane * 8);
            const float4* hp1 = (const float4*)(g_h + (size_t)r1 * NH + lane * 8);
            float4 h00 = __ldg(hp0), h01 = __ldg(hp0 + 1);
            float4 h10 = __ldg(hp1), h11 = __ldg(hp1 + 1);
            accA0.x = fmaf(a0, h00.x, accA0.x); accA0.y = fmaf(a0, h00.y, accA0.y);
            accA0.z = fmaf(a0, h00.z, accA0.z); accA0.w = fmaf(a0, h00.w, accA0.w);
            accA1.x = fmaf(a0, h01.x, accA1.x); accA1.y = fmaf(a0, h01.y, accA1.y);
            accA1.z = fmaf(a0, h01.z, accA1.z); accA1.w = fmaf(a0, h01.w, accA1.w);
            accB0.x = fmaf(a1, h10.x, accB0.x); accB0.y = fmaf(a1, h10.y, accB0.y);
            accB0.z = fmaf(a1, h10.z, accB0.z); accB0.w = fmaf(a1, h10.w, accB0.w);
            accB1.x = fmaf(a1, h11.x, accB1.x); accB1.y = fmaf(a1, h11.y, accB1.y);
            accB1.z = fmaf(a1, h11.z, accB1.z); accB1.w = fmaf(a1, h11.w, accB1.w);
        }
        if (j < m) {
            int p0 = __shfl_sync(0xffffffffu, pm, j);
            int r0 = __shfl_sync(0xffffffffu, rr, j);
            float a0 = __ldg(g_att + (size_t)p0 * 8 + head);
            const float4* hp0 = (const float4*)(g_h + (size_t)r0 * NH + lane * 8);
            float4 h00 = __ldg(hp0), h01 = __ldg(hp0 + 1);
            accA0.x = fmaf(a0, h00.x, accA0.x); accA0.y = fmaf(a0, h00.y, accA0.y);
            accA0.z = fmaf(a0, h00.z, accA0.z); accA0.w = fmaf(a0, h00.w, accA0.w);
            accA1.x = fmaf(a0, h01.x, accA1.x); accA1.y = fmaf(a0, h01.y, accA1.y);
            accA1.z = fmaf(a0, h01.z, accA1.z); accA1.w = fmaf(a0, h01.w, accA1.w);
        }
    }

    float inv = (cnt > 0) ? (1.f / g_denom[n * NHEAD + head]) : 0.f;
    float4 o0, o1;
    o0.x = (accA0.x + accB0.x) * inv; o0.y = (accA0.y + accB0.y) * inv;
    o0.z = (accA0.z + accB0.z) * inv; o0.w = (accA0.w + accB0.w) * inv;
    o1.x = (accA1.x + accB1.x) * inv; o1.y = (accA1.y + accB1.y) * inv;
    o1.z = (accA1.z + accB1.z) * inv; o1.w = (accA1.w + accB1.w) * inv;
    float* op = out + (size_t)n * NH + lane * 8;
    *(float4*)op = o0;
    *(float4*)(op + 4) = o1;
}

// ---------------- launch ----------------
extern "C" void kernel_launch(void* const* d_in, const int* in_sizes, int n_in,
                              void* d_out, int out_size) {
    const float* x   = (const float*)d_in[0];
    const float* W   = (const float*)d_in[1];
    const float* We  = (const float*)d_in[2];
    const float* emb = (const float*)d_in[3];
    const float* a_l = (const float*)d_in[4];
    const float* a_r = (const float*)d_in[5];
    const float* a_e = (const float*)d_in[6];
    const int* row = (const int*)d_in[7];
    const int* col = (const int*)d_in[8];
    const int* et  = (const int*)d_in[9];
    float* out = (float*)d_out;
    float* attn_out = (out_size >= N_NODES * NH + N_EDGES * NHEAD)
                          ? (out + (size_t)N_NODES * NH)
                          : nullptr;

    const int EB = (N_EDGES + 255) / 256;

    k_init<<<(N_NODES * NHEAD + 255) / 256, 256>>>(emb, We, a_e);
    k_wsplit<<<(D_IN * NH + 255) / 256, 256>>>(W);

    dim3 ggrid(2, (N_NODES + 127) / 128);
    k_gemm_tc<<<ggrid, 256>>>(x);
    k_hlhr<<<(N_NODES + 7) / 8, 256>>>(a_l, a_r);

    k_hist<<<EB, 256>>>(col);
    k_scanA<<<NB, 256>>>();
    k_scanB<<<1, 256>>>();
    k_scanC<<<NB, 256>>>();
    k_edge<<<EB, 256>>>(row, col, et);

    if (attn_out) k_norm<<<EB, 256>>>(col, attn_out);
    k_agg<<<(N_NODES + 7) / 8, 256>>>(out);
}

// round 8
// speedup vs baseline: 1.6104x; 1.0710x over previous
#include <cuda_runtime.h>
#include <math.h>

#define N_NODES 50000
#define N_EDGES 800000
#define NHEAD 8
#define D_OUT 32
#define D_IN 256
#define NH 256            // NHEAD * D_OUT
#define E_FEAT 64
#define N_ETYPES 5
#define NEG 0.2f
#define NB 196            // ceil(N_NODES / 256)

// ---------------- scratch (device globals; no allocation allowed) ----------------
__device__ float    g_h[N_NODES * NH];          // projected node features [N,8,32]
__device__ float    g_hl[N_NODES * NHEAD];
__device__ float    g_hr[N_NODES * NHEAD];
__device__ float    g_he[N_ETYPES * NHEAD];
__device__ float    g_att[N_EDGES * NHEAD];     // ex, original edge order
__device__ float    g_denom[N_NODES * NHEAD];   // written by k_agg (no atomics)
__device__ int      g_counts[N_NODES];
__device__ int      g_offs[N_NODES];
__device__ int      g_cursor[N_NODES];
__device__ int      g_perm[N_EDGES];            // CSR pos -> original edge id
__device__ int      g_rows[N_EDGES];            // row[] permuted into CSR order
__device__ int      g_bsums[256];
__device__ uint2    g_Wsp[D_IN * NH];           // W pre-split into tf32 (hi, lo)

// ---------------- tf32 helpers ----------------
__device__ __forceinline__ unsigned cvt_tf32(float x) {
    unsigned r;
    asm("cvt.rna.tf32.f32 %0, %1;" : "=r"(r) : "f"(x));
    return r;
}
__device__ __forceinline__ void tf32_split(float x, unsigned& hi, unsigned& lo) {
    hi = cvt_tf32(x);
    lo = cvt_tf32(x - __uint_as_float(hi));
}
__device__ __forceinline__ void mma_tf32(float* d, const unsigned* a, const unsigned* b) {
    asm volatile(
        "mma.sync.aligned.m16n8k8.row.col.f32.tf32.tf32.f32 "
        "{%0,%1,%2,%3}, {%4,%5,%6,%7}, {%8,%9}, {%0,%1,%2,%3};"
        : "+f"(d[0]), "+f"(d[1]), "+f"(d[2]), "+f"(d[3])
        : "r"(a[0]), "r"(a[1]), "r"(a[2]), "r"(a[3]), "r"(b[0]), "r"(b[1]));
}

// ---------------- init (+ fused he: per-etype attention dots) ----------------
__global__ void k_init(const float* __restrict__ emb, const float* __restrict__ We,
                       const float* __restrict__ a_e) {
    int i = blockIdx.x * blockDim.x + threadIdx.x;
    if (i < N_NODES) g_counts[i] = 0;
    if (blockIdx.x < N_ETYPES * NHEAD) {
        int t = blockIdx.x >> 3, hd = blockIdx.x & 7;
        __shared__ float r2[2];
        float s = 0.f;
        if (threadIdx.x < 64) {
            int f = threadIdx.x;
            float ev = 0.f;
#pragma unroll 8
            for (int k = 0; k < E_FEAT; k++)
                ev += emb[t * E_FEAT + k] * We[k * (E_FEAT * NHEAD) + hd * E_FEAT + f];
            s = ev * a_e[hd * E_FEAT + f];
#pragma unroll
            for (int o = 16; o >= 1; o >>= 1) s += __shfl_xor_sync(0xffffffffu, s, o);
            if ((threadIdx.x & 31) == 0) r2[threadIdx.x >> 5] = s;
        }
        __syncthreads();
        if (threadIdx.x == 0) g_he[t * NHEAD + hd] = r2[0] + r2[1];
    }
}

// ---------------- pre-split W into tf32 hi/lo ----------------
__global__ void k_wsplit(const float* __restrict__ W) {
    int i = blockIdx.x * blockDim.x + threadIdx.x;
    if (i < D_IN * NH) {
        unsigned hi, lo;
        tf32_split(W[i], hi, lo);
        g_Wsp[i] = make_uint2(hi, lo);
    }
}

// -------- GEMM: h = x @ W via 3xTF32 (smem X + pre-split W) + fused hl/hr ---------
__global__ __launch_bounds__(256, 2) void k_gemm_tc(const float* __restrict__ X,
                                                    const float* __restrict__ a_l,
                                                    const float* __restrict__ a_r) {
    __shared__ float Xs[8][136];
    int warp = threadIdx.x >> 5, lane = threadIdx.x & 31;
    int gid = lane >> 2, tig = lane & 3;
    int wm = (warp >> 1) * 32;
    int wn = (warp & 1) * 64;
    int m0 = blockIdx.y * 128;
    int n0 = blockIdx.x * 128;

    float acc[2][8][4];
#pragma unroll
    for (int mt = 0; mt < 2; mt++)
#pragma unroll
        for (int nt = 0; nt < 8; nt++)
#pragma unroll
            for (int c = 0; c < 4; c++) acc[mt][nt][c] = 0.f;

    int srow = threadIdx.x >> 1;
    int skq = (threadIdx.x & 1) * 4;
    bool srow_ok = (m0 + srow) < N_NODES;
    const float* xp = X + (size_t)(m0 + srow) * D_IN + skq;

    for (int k0 = 0; k0 < D_IN; k0 += 8) {
        float4 v = make_float4(0.f, 0.f, 0.f, 0.f);
        if (srow_ok) v = *(const float4*)(xp + k0);
        Xs[skq + 0][srow] = v.x;
        Xs[skq + 1][srow] = v.y;
        Xs[skq + 2][srow] = v.z;
        Xs[skq + 3][srow] = v.w;
        __syncthreads();

        unsigned ah[2][4], al[2][4];
#pragma unroll
        for (int mt = 0; mt < 2; mt++) {
            int r = wm + mt * 16 + gid;
            tf32_split(Xs[tig][r],         ah[mt][0], al[mt][0]);
            tf32_split(Xs[tig][r + 8],     ah[mt][1], al[mt][1]);
            tf32_split(Xs[tig + 4][r],     ah[mt][2], al[mt][2]);
            tf32_split(Xs[tig + 4][r + 8], ah[mt][3], al[mt][3]);
        }
#pragma unroll
        for (int nt = 0; nt < 8; nt++) {
            int c = n0 + wn + nt * 8 + gid;
            uint2 b0 = g_Wsp[(size_t)(k0 + tig) * NH + c];
            uint2 b1 = g_Wsp[(size_t)(k0 + tig + 4) * NH + c];
            unsigned bh[2] = {b0.x, b1.x};
            unsigned bl[2] = {b0.y, b1.y};
#pragma unroll
            for (int mt = 0; mt < 2; mt++) {
                mma_tf32(acc[mt][nt], ah[mt], bh);
                mma_tf32(acc[mt][nt], al[mt], bh);
                mma_tf32(acc[mt][nt], ah[mt], bl);
            }
        }
        __syncthreads();
    }

    // store h
#pragma unroll
    for (int mt = 0; mt < 2; mt++) {
        int r1 = m0 + wm + mt * 16 + gid;
        int r2 = r1 + 8;
#pragma unroll
        for (int nt = 0; nt < 8; nt++) {
            int c = n0 + wn + nt * 8 + 2 * tig;
            if (r1 < N_NODES)
                *(float2*)&g_h[(size_t)r1 * NH + c] = make_float2(acc[mt][nt][0], acc[mt][nt][1]);
            if (r2 < N_NODES)
                *(float2*)&g_h[(size_t)r2 * NH + c] = make_float2(acc[mt][nt][2], acc[mt][nt][3]);
        }
    }

    // fused hl/hr: this warp's 64 cols = heads headA, headA+1
    int headA = (n0 + wn) >> 5;
#pragma unroll
    for (int hh = 0; hh < 2; hh++) {
        int head = headA + hh;
#pragma unroll
        for (int mt = 0; mt < 2; mt++) {
            float l1 = 0.f, r1v = 0.f, l2 = 0.f, r2v = 0.f;
#pragma unroll
            for (int q = 0; q < 4; q++) {
                int nt = hh * 4 + q;
                int d = q * 8 + 2 * tig;
                float al0 = __ldg(a_l + head * D_OUT + d);
                float al1 = __ldg(a_l + head * D_OUT + d + 1);
                float ar0 = __ldg(a_r + head * D_OUT + d);
                float ar1 = __ldg(a_r + head * D_OUT + d + 1);
                l1  += acc[mt][nt][0] * al0 + acc[mt][nt][1] * al1;
                r1v += acc[mt][nt][0] * ar0 + acc[mt][nt][1] * ar1;
                l2  += acc[mt][nt][2] * al0 + acc[mt][nt][3] * al1;
                r2v += acc[mt][nt][2] * ar0 + acc[mt][nt][3] * ar1;
            }
#pragma unroll
            for (int o = 1; o <= 2; o <<= 1) {
                l1  += __shfl_xor_sync(0xffffffffu, l1, o);
                r1v += __shfl_xor_sync(0xffffffffu, r1v, o);
                l2  += __shfl_xor_sync(0xffffffffu, l2, o);
                r2v += __shfl_xor_sync(0xffffffffu, r2v, o);
            }
            if (tig == 0) {
                int rr1 = m0 + wm + mt * 16 + gid;
                int rr2 = rr1 + 8;
                if (rr1 < N_NODES) { g_hl[rr1 * NHEAD + head] = l1; g_hr[rr1 * NHEAD + head] = r1v; }
                if (rr2 < N_NODES) { g_hl[rr2 * NHEAD + head] = l2; g_hr[rr2 * NHEAD + head] = r2v; }
            }
        }
    }
}

// ---------------- histogram over col ----------------
__global__ void k_hist(const int* __restrict__ col) {
    int e = blockIdx.x * blockDim.x + threadIdx.x;
    if (e < N_EDGES) atomicAdd(&g_counts[col[e]], 1);
}

// ---------------- scans (CSR offsets over col histogram) ----------------
__global__ void k_scanA() {
    int i = blockIdx.x * 256 + threadIdx.x;
    int v = (i < N_NODES) ? g_counts[i] : 0;
    int x = v;
    int lane = threadIdx.x & 31, wid = threadIdx.x >> 5;
#pragma unroll
    for (int o = 1; o < 32; o <<= 1) {
        int y = __shfl_up_sync(0xffffffffu, x, o);
        if (lane >= o) x += y;
    }
    __shared__ int ws[8];
    if (lane == 31) ws[wid] = x;
    __syncthreads();
    if (threadIdx.x == 0) {
        int s = 0;
        for (int w = 0; w < 8; w++) { int t = ws[w]; ws[w] = s; s += t; }
    }
    __syncthreads();
    int excl = x - v + ws[wid];
    if (i < N_NODES) g_offs[i] = excl;
    if (threadIdx.x == 255) g_bsums[blockIdx.x] = excl + v;
}

__global__ void k_scanB() {
    int i = threadIdx.x;
    int v = (i < NB) ? g_bsums[i] : 0;
    int x = v;
    int lane = threadIdx.x & 31, wid = threadIdx.x >> 5;
#pragma unroll
    for (int o = 1; o < 32; o <<= 1) {
        int y = __shfl_up_sync(0xffffffffu, x, o);
        if (lane >= o) x += y;
    }
    __shared__ int ws[8];
    if (lane == 31) ws[wid] = x;
    __syncthreads();
    if (threadIdx.x == 0) {
        int s = 0;
        for (int w = 0; w < 8; w++) { int t = ws[w]; ws[w] = s; s += t; }
    }
    __syncthreads();
    int excl = x - v + ws[wid];
    if (i < NB) g_bsums[i] = excl;
}

__global__ void k_scanC() {
    int i = blockIdx.x * 256 + threadIdx.x;
    if (i < N_NODES) {
        int o = g_offs[i] + g_bsums[blockIdx.x];
        g_offs[i] = o;
        g_cursor[i] = o;
    }
}

// ------- fused edge pass: logits + exp (no max needed) + CSR scatter ---------------
__global__ void k_edge(const int* __restrict__ row, const int* __restrict__ col,
                       const int* __restrict__ et) {
    int e = blockIdx.x * blockDim.x + threadIdx.x;
    if (e >= N_EDGES) return;
    int rr = row[e], cc = col[e], tt = et[e];
    int pos = atomicAdd(&g_cursor[cc], 1);
    g_perm[pos] = e;
    g_rows[pos] = rr;
    const float4* hl4 = (const float4*)(g_hl + rr * NHEAD);
    const float4* hr4 = (const float4*)(g_hr + cc * NHEAD);
    const float4* he4 = (const float4*)(g_he + tt * NHEAD);
    float v[8];
#pragma unroll
    for (int q = 0; q < 2; q++) {
        float4 a = hl4[q], b = hr4[q], c = he4[q];
        float s;
        s = a.x + b.x + c.x; s = s > 0.f ? s : NEG * s; v[q * 4 + 0] = __expf(s);
        s = a.y + b.y + c.y; s = s > 0.f ? s : NEG * s; v[q * 4 + 1] = __expf(s);
        s = a.z + b.z + c.z; s = s > 0.f ? s : NEG * s; v[q * 4 + 2] = __expf(s);
        s = a.w + b.w + c.w; s = s > 0.f ? s : NEG * s; v[q * 4 + 3] = __expf(s);
    }
    *(float4*)(g_att + (size_t)e * 8 + 0) = make_float4(v[0], v[1], v[2], v[3]);
    *(float4*)(g_att + (size_t)e * 8 + 4) = make_float4(v[4], v[5], v[6], v[7]);
}

// ------- CSR aggregation: warp per node, all heads; computes denom itself ----------
__global__ __launch_bounds__(256) void k_agg(float* __restrict__ out) {
    int n = blockIdx.x * 8 + (threadIdx.x >> 5);
    if (n >= N_NODES) return;
    int lane = threadIdx.x & 31;
    int head = lane >> 2;               // 8 floats per lane -> head = lane/4
    int start = g_offs[n];
    int cnt = g_counts[n];

    float4 accA0 = make_float4(0.f, 0.f, 0.f, 0.f), accA1 = accA0;
    float4 accB0 = accA0, accB1 = accA0;
    float dsum = 0.f;

    for (int base = 0; base < cnt; base += 32) {
        int m = min(cnt - base, 32);
        int pm = 0, rr = 0;
        if (lane < m) {
            pm = g_perm[start + base + lane];
            rr = g_rows[start + base + lane];
        }
        int j = 0;
        for (; j + 2 <= m; j += 2) {
            int p0 = __shfl_sync(0xffffffffu, pm, j);
            int r0 = __shfl_sync(0xffffffffu, rr, j);
            int p1 = __shfl_sync(0xffffffffu, pm, j + 1);
            int r1 = __shfl_sync(0xffffffffu, rr, j + 1);
            float a0 = __ldg(g_att + (size_t)p0 * 8 + head);
            float a1 = __ldg(g_att + (size_t)p1 * 8 + head);
            dsum += a0 + a1;
            const float4* hp0 = (const float4*)(g_h + (size_t)r0 * NH + lane * 8);
            const float4* hp1 = (const float4*)(g_h + (size_t)r1 * NH + lane * 8);
            float4 h00 = __ldg(hp0), h01 = __ldg(hp0 + 1);
            float4 h10 = __ldg(hp1), h11 = __ldg(hp1 + 1);
            accA0.x = fmaf(a0, h00.x, accA0.x); accA0.y = fmaf(a0, h00.y, accA0.y);
            accA0.z = fmaf(a0, h00.z, accA0.z); accA0.w = fmaf(a0, h00.w, accA0.w);
            accA1.x = fmaf(a0, h01.x, accA1.x); accA1.y = fmaf(a0, h01.y, accA1.y);
            accA1.z = fmaf(a0, h01.z, accA1.z); accA1.w = fmaf(a0, h01.w, accA1.w);
            accB0.x = fmaf(a1, h10.x, accB0.x); accB0.y = fmaf(a1, h10.y, accB0.y);
            accB0.z = fmaf(a1, h10.z, accB0.z); accB0.w = fmaf(a1, h10.w, accB0.w);
            accB1.x = fmaf(a1, h11.x, accB1.x); accB1.y = fmaf(a1, h11.y, accB1.y);
            accB1.z = fmaf(a1, h11.z, accB1.z); accB1.w = fmaf(a1, h11.w, accB1.w);
        }
        if (j < m) {
            int p0 = __shfl_sync(0xffffffffu, pm, j);
            int r0 = __shfl_sync(0xffffffffu, rr, j);
            float a0 = __ldg(g_att + (size_t)p0 * 8 + head);
            dsum += a0;
            const float4* hp0 = (const float4*)(g_h + (size_t)r0 * NH + lane * 8);
            float4 h00 = __ldg(hp0), h01 = __ldg(hp0 + 1);
            accA0.x = fmaf(a0, h00.x, accA0.x); accA0.y = fmaf(a0, h00.y, accA0.y);
            accA0.z = fmaf(a0, h00.z, accA0.z); accA0.w = fmaf(a0, h00.w, accA0.w);
            accA1.x = fmaf(a0, h01.x, accA1.x); accA1.y = fmaf(a0, h01.y, accA1.y);
            accA1.z = fmaf(a0, h01.z, accA1.z); accA1.w = fmaf(a0, h01.w, accA1.w);
        }
    }

    float inv = (cnt > 0) ? (1.f / dsum) : 0.f;
    if ((lane & 3) == 0) g_denom[n * NHEAD + head] = (cnt > 0) ? dsum : 1.f;
    float4 o0, o1;
    o0.x = (accA0.x + accB0.x) * inv; o0.y = (accA0.y + accB0.y) * inv;
    o0.z = (accA0.z + accB0.z) * inv; o0.w = (accA0.w + accB0.w) * inv;
    o1.x = (accA1.x + accB1.x) * inv; o1.y = (accA1.y + accB1.y) * inv;
    o1.z = (accA1.z + accB1.z) * inv; o1.w = (accA1.w + accB1.w) * inv;
    float* op = out + (size_t)n * NH + lane * 8;
    *(float4*)op = o0;
    *(float4*)(op + 4) = o1;
}

// ---------------- attn output: ex / denom (after k_agg fills g_denom) -------------
__global__ void k_norm(const int* __restrict__ col, float* __restrict__ attn_out) {
    int e = blockIdx.x * blockDim.x + threadIdx.x;
    if (e >= N_EDGES) return;
    int cc = col[e];
    float4 e0 = *(const float4*)(g_att + (size_t)e * 8 + 0);
    float4 e1 = *(const float4*)(g_att + (size_t)e * 8 + 4);
    const float4* d4 = (const float4*)(g_denom + cc * NHEAD);
    float4 d0 = d4[0], d1 = d4[1];
    float4 a0 = make_float4(e0.x / d0.x, e0.y / d0.y, e0.z / d0.z, e0.w / d0.w);
    float4 a1 = make_float4(e1.x / d1.x, e1.y / d1.y, e1.z / d1.z, e1.w / d1.w);
    *(float4*)(attn_out + (size_t)e * 8 + 0) = a0;
    *(float4*)(attn_out + (size_t)e * 8 + 4) = a1;
}

// ---------------- launch ----------------
extern "C" void kernel_launch(void* const* d_in, const int* in_sizes, int n_in,
                              void* d_out, int out_size) {
    const float* x   = (const float*)d_in[0];
    const float* W   = (const float*)d_in[1];
    const float* We  = (const float*)d_in[2];
    const float* emb = (const float*)d_in[3];
    const float* a_l = (const float*)d_in[4];
    const float* a_r = (const float*)d_in[5];
    const float* a_e = (const float*)d_in[6];
    const int* row = (const int*)d_in[7];
    const int* col = (const int*)d_in[8];
    const int* et  = (const int*)d_in[9];
    float* out = (float*)d_out;
    float* attn_out = (out_size >= N_NODES * NH + N_EDGES * NHEAD)
                          ? (out + (size_t)N_NODES * NH)
                          : nullptr;

    const int EB = (N_EDGES + 255) / 256;

    k_init<<<(N_NODES + 255) / 256, 256>>>(emb, We, a_e);
    k_wsplit<<<(D_IN * NH + 255) / 256, 256>>>(W);

    dim3 ggrid(2, (N_NODES + 127) / 128);
    k_gemm_tc<<<ggrid, 256>>>(x, a_l, a_r);

    k_hist<<<EB, 256>>>(col);
    k_scanA<<<NB, 256>>>();
    k_scanB<<<1, 256>>>();
    k_scanC<<<NB, 256>>>();
    k_edge<<<EB, 256>>>(row, col, et);

    k_agg<<<(N_NODES + 7) / 8, 256>>>(out);
    if (attn_out) k_norm<<<EB, 256>>>(col, attn_out);
}

// round 9
// speedup vs baseline: 1.6405x; 1.0187x over previous
#include <cuda_runtime.h>
#include <math.h>

#define N_NODES 50000
#define N_EDGES 800000
#define NHEAD 8
#define D_OUT 32
#define D_IN 256
#define NH 256            // NHEAD * D_OUT
#define E_FEAT 64
#define N_ETYPES 5
#define NEG 0.2f
#define NB 196            // ceil(N_NODES / 256)

// ---------------- scratch (device globals; no allocation allowed) ----------------
__device__ float    g_h[N_NODES * NH];          // projected node features [N,8,32]
__device__ float    g_hl[N_NODES * NHEAD];
__device__ float    g_hr[N_NODES * NHEAD];
__device__ float    g_he[N_ETYPES * NHEAD];
__device__ float    g_denom[N_NODES * NHEAD];   // written by k_agg (no atomics)
__device__ int      g_counts[N_NODES];
__device__ int      g_offs[N_NODES];
__device__ int      g_cursor[N_NODES];
__device__ int      g_rt[N_EDGES];              // CSR order: row | (etype<<16)
__device__ int      g_bsums[256];
__device__ uint2    g_Wsp[D_IN * NH];           // W pre-split into tf32 (hi, lo)

// ---------------- tf32 helpers ----------------
__device__ __forceinline__ unsigned cvt_tf32(float x) {
    unsigned r;
    asm("cvt.rna.tf32.f32 %0, %1;" : "=r"(r) : "f"(x));
    return r;
}
__device__ __forceinline__ void tf32_split(float x, unsigned& hi, unsigned& lo) {
    hi = cvt_tf32(x);
    lo = cvt_tf32(x - __uint_as_float(hi));
}
__device__ __forceinline__ void mma_tf32(float* d, const unsigned* a, const unsigned* b) {
    asm volatile(
        "mma.sync.aligned.m16n8k8.row.col.f32.tf32.tf32.f32 "
        "{%0,%1,%2,%3}, {%4,%5,%6,%7}, {%8,%9}, {%0,%1,%2,%3};"
        : "+f"(d[0]), "+f"(d[1]), "+f"(d[2]), "+f"(d[3])
        : "r"(a[0]), "r"(a[1]), "r"(a[2]), "r"(a[3]), "r"(b[0]), "r"(b[1]));
}

// ---------------- init (+ fused he: per-etype attention dots) ----------------
__global__ void k_init(const float* __restrict__ emb, const float* __restrict__ We,
                       const float* __restrict__ a_e) {
    int i = blockIdx.x * blockDim.x + threadIdx.x;
    if (i < N_NODES) g_counts[i] = 0;
    if (blockIdx.x < N_ETYPES * NHEAD) {
        int t = blockIdx.x >> 3, hd = blockIdx.x & 7;
        __shared__ float r2[2];
        float s = 0.f;
        if (threadIdx.x < 64) {
            int f = threadIdx.x;
            float ev = 0.f;
#pragma unroll 8
            for (int k = 0; k < E_FEAT; k++)
                ev += emb[t * E_FEAT + k] * We[k * (E_FEAT * NHEAD) + hd * E_FEAT + f];
            s = ev * a_e[hd * E_FEAT + f];
#pragma unroll
            for (int o = 16; o >= 1; o >>= 1) s += __shfl_xor_sync(0xffffffffu, s, o);
            if ((threadIdx.x & 31) == 0) r2[threadIdx.x >> 5] = s;
        }
        __syncthreads();
        if (threadIdx.x == 0) g_he[t * NHEAD + hd] = r2[0] + r2[1];
    }
}

// ---------------- pre-split W into tf32 hi/lo ----------------
__global__ void k_wsplit(const float* __restrict__ W) {
    int i = blockIdx.x * blockDim.x + threadIdx.x;
    if (i < D_IN * NH) {
        unsigned hi, lo;
        tf32_split(W[i], hi, lo);
        g_Wsp[i] = make_uint2(hi, lo);
    }
}

// -------- GEMM: h = x @ W via 3xTF32 (smem X + pre-split W) + fused hl/hr ---------
__global__ __launch_bounds__(256, 2) void k_gemm_tc(const float* __restrict__ X,
                                                    const float* __restrict__ a_l,
                                                    const float* __restrict__ a_r) {
    __shared__ float Xs[8][136];
    int warp = threadIdx.x >> 5, lane = threadIdx.x & 31;
    int gid = lane >> 2, tig = lane & 3;
    int wm = (warp >> 1) * 32;
    int wn = (warp & 1) * 64;
    int m0 = blockIdx.y * 128;
    int n0 = blockIdx.x * 128;

    float acc[2][8][4];
#pragma unroll
    for (int mt = 0; mt < 2; mt++)
#pragma unroll
        for (int nt = 0; nt < 8; nt++)
#pragma unroll
            for (int c = 0; c < 4; c++) acc[mt][nt][c] = 0.f;

    int srow = threadIdx.x >> 1;
    int skq = (threadIdx.x & 1) * 4;
    bool srow_ok = (m0 + srow) < N_NODES;
    const float* xp = X + (size_t)(m0 + srow) * D_IN + skq;

    for (int k0 = 0; k0 < D_IN; k0 += 8) {
        float4 v = make_float4(0.f, 0.f, 0.f, 0.f);
        if (srow_ok) v = *(const float4*)(xp + k0);
        Xs[skq + 0][srow] = v.x;
        Xs[skq + 1][srow] = v.y;
        Xs[skq + 2][srow] = v.z;
        Xs[skq + 3][srow] = v.w;
        __syncthreads();

        unsigned ah[2][4], al[2][4];
#pragma unroll
        for (int mt = 0; mt < 2; mt++) {
            int r = wm + mt * 16 + gid;
            tf32_split(Xs[tig][r],         ah[mt][0], al[mt][0]);
            tf32_split(Xs[tig][r + 8],     ah[mt][1], al[mt][1]);
            tf32_split(Xs[tig + 4][r],     ah[mt][2], al[mt][2]);
            tf32_split(Xs[tig + 4][r + 8], ah[mt][3], al[mt][3]);
        }
#pragma unroll
        for (int nt = 0; nt < 8; nt++) {
            int c = n0 + wn + nt * 8 + gid;
            uint2 b0 = g_Wsp[(size_t)(k0 + tig) * NH + c];
            uint2 b1 = g_Wsp[(size_t)(k0 + tig + 4) * NH + c];
            unsigned bh[2] = {b0.x, b1.x};
            unsigned bl[2] = {b0.y, b1.y};
#pragma unroll
            for (int mt = 0; mt < 2; mt++) {
                mma_tf32(acc[mt][nt], ah[mt], bh);
                mma_tf32(acc[mt][nt], al[mt], bh);
                mma_tf32(acc[mt][nt], ah[mt], bl);
            }
        }
        __syncthreads();
    }

    // store h
#pragma unroll
    for (int mt = 0; mt < 2; mt++) {
        int r1 = m0 + wm + mt * 16 + gid;
        int r2 = r1 + 8;
#pragma unroll
        for (int nt = 0; nt < 8; nt++) {
            int c = n0 + wn + nt * 8 + 2 * tig;
            if (r1 < N_NODES)
                *(float2*)&g_h[(size_t)r1 * NH + c] = make_float2(acc[mt][nt][0], acc[mt][nt][1]);
            if (r2 < N_NODES)
                *(float2*)&g_h[(size_t)r2 * NH + c] = make_float2(acc[mt][nt][2], acc[mt][nt][3]);
        }
    }

    // fused hl/hr: this warp's 64 cols = heads headA, headA+1
    int headA = (n0 + wn) >> 5;
#pragma unroll
    for (int hh = 0; hh < 2; hh++) {
        int head = headA + hh;
#pragma unroll
        for (int mt = 0; mt < 2; mt++) {
            float l1 = 0.f, r1v = 0.f, l2 = 0.f, r2v = 0.f;
#pragma unroll
            for (int q = 0; q < 4; q++) {
                int nt = hh * 4 + q;
                int d = q * 8 + 2 * tig;
                float al0 = __ldg(a_l + head * D_OUT + d);
                float al1 = __ldg(a_l + head * D_OUT + d + 1);
                float ar0 = __ldg(a_r + head * D_OUT + d);
                float ar1 = __ldg(a_r + head * D_OUT + d + 1);
                l1  += acc[mt][nt][0] * al0 + acc[mt][nt][1] * al1;
                r1v += acc[mt][nt][0] * ar0 + acc[mt][nt][1] * ar1;
                l2  += acc[mt][nt][2] * al0 + acc[mt][nt][3] * al1;
                r2v += acc[mt][nt][2] * ar0 + acc[mt][nt][3] * ar1;
            }
#pragma unroll
            for (int o = 1; o <= 2; o <<= 1) {
                l1  += __shfl_xor_sync(0xffffffffu, l1, o);
                r1v += __shfl_xor_sync(0xffffffffu, r1v, o);
                l2  += __shfl_xor_sync(0xffffffffu, l2, o);
                r2v += __shfl_xor_sync(0xffffffffu, r2v, o);
            }
            if (tig == 0) {
                int rr1 = m0 + wm + mt * 16 + gid;
                int rr2 = rr1 + 8;
                if (rr1 < N_NODES) { g_hl[rr1 * NHEAD + head] = l1; g_hr[rr1 * NHEAD + head] = r1v; }
                if (rr2 < N_NODES) { g_hl[rr2 * NHEAD + head] = l2; g_hr[rr2 * NHEAD + head] = r2v; }
            }
        }
    }
}

// ---------------- histogram over col ----------------
__global__ void k_hist(const int* __restrict__ col) {
    int e = blockIdx.x * blockDim.x + threadIdx.x;
    if (e < N_EDGES) atomicAdd(&g_counts[col[e]], 1);
}

// ---------------- scans (CSR offsets over col histogram) ----------------
__global__ void k_scanA() {
    int i = blockIdx.x * 256 + threadIdx.x;
    int v = (i < N_NODES) ? g_counts[i] : 0;
    int x = v;
    int lane = threadIdx.x & 31, wid = threadIdx.x >> 5;
#pragma unroll
    for (int o = 1; o < 32; o <<= 1) {
        int y = __shfl_up_sync(0xffffffffu, x, o);
        if (lane >= o) x += y;
    }
    __shared__ int ws[8];
    if (lane == 31) ws[wid] = x;
    __syncthreads();
    if (threadIdx.x == 0) {
        int s = 0;
        for (int w = 0; w < 8; w++) { int t = ws[w]; ws[w] = s; s += t; }
    }
    __syncthreads();
    int excl = x - v + ws[wid];
    if (i < N_NODES) g_offs[i] = excl;
    if (threadIdx.x == 255) g_bsums[blockIdx.x] = excl + v;
}

__global__ void k_scanB() {
    int i = threadIdx.x;
    int v = (i < NB) ? g_bsums[i] : 0;
    int x = v;
    int lane = threadIdx.x & 31, wid = threadIdx.x >> 5;
#pragma unroll
    for (int o = 1; o < 32; o <<= 1) {
        int y = __shfl_up_sync(0xffffffffu, x, o);
        if (lane >= o) x += y;
    }
    __shared__ int ws[8];
    if (lane == 31) ws[wid] = x;
    __syncthreads();
    if (threadIdx.x == 0) {
        int s = 0;
        for (int w = 0; w < 8; w++) { int t = ws[w]; ws[w] = s; s += t; }
    }
    __syncthreads();
    int excl = x - v + ws[wid];
    if (i < NB) g_bsums[i] = excl;
}

__global__ void k_scanC() {
    int i = blockIdx.x * 256 + threadIdx.x;
    if (i < N_NODES) {
        int o = g_offs[i] + g_bsums[blockIdx.x];
        g_offs[i] = o;
        g_cursor[i] = o;
    }
}

// ---------------- CSR scatter: pack (row, etype) per position ----------------
__global__ void k_scatter(const int* __restrict__ row, const int* __restrict__ col,
                          const int* __restrict__ et) {
    int e = blockIdx.x * blockDim.x + threadIdx.x;
    if (e >= N_EDGES) return;
    int cc = col[e];
    int pos = atomicAdd(&g_cursor[cc], 1);
    g_rt[pos] = row[e] | (et[e] << 16);
}

// ------- CSR aggregation: warp per node; recomputes ex inline; owns denom ----------
__global__ __launch_bounds__(256) void k_agg(float* __restrict__ out) {
    __shared__ float s_he[N_ETYPES * NHEAD];
    if (threadIdx.x < N_ETYPES * NHEAD) s_he[threadIdx.x] = g_he[threadIdx.x];
    __syncthreads();

    int n = blockIdx.x * 8 + (threadIdx.x >> 5);
    if (n >= N_NODES) return;
    int lane = threadIdx.x & 31;
    int head = lane >> 2;               // 8 dims per lane -> head = lane/4
    int start = g_offs[n];
    int cnt = g_counts[n];
    float hrv = g_hr[n * NHEAD + head];   // warp-constant per head group

    float4 accA0 = make_float4(0.f, 0.f, 0.f, 0.f), accA1 = accA0;
    float4 accB0 = accA0, accB1 = accA0;
    float dsum = 0.f;

    for (int base = 0; base < cnt; base += 32) {
        int m = min(cnt - base, 32);
        int prt = 0;
        if (lane < m) prt = g_rt[start + base + lane];
        int j = 0;
        for (; j + 2 <= m; j += 2) {
            int q0 = __shfl_sync(0xffffffffu, prt, j);
            int q1 = __shfl_sync(0xffffffffu, prt, j + 1);
            int r0 = q0 & 0xFFFF, t0 = q0 >> 16;
            int r1 = q1 & 0xFFFF, t1 = q1 >> 16;
            float s0 = __ldg(g_hl + r0 * NHEAD + head) + hrv + s_he[t0 * NHEAD + head];
            float s1 = __ldg(g_hl + r1 * NHEAD + head) + hrv + s_he[t1 * NHEAD + head];
            s0 = s0 > 0.f ? s0 : NEG * s0;
            s1 = s1 > 0.f ? s1 : NEG * s1;
            float a0 = __expf(s0), a1 = __expf(s1);
            dsum += a0 + a1;
            const float4* hp0 = (const float4*)(g_h + (size_t)r0 * NH + lane * 8);
            const float4* hp1 = (const float4*)(g_h + (size_t)r1 * NH + lane * 8);
            float4 h00 = __ldg(hp0), h01 = __ldg(hp0 + 1);
            float4 h10 = __ldg(hp1), h11 = __ldg(hp1 + 1);
            accA0.x = fmaf(a0, h00.x, accA0.x); accA0.y = fmaf(a0, h00.y, accA0.y);
            accA0.z = fmaf(a0, h00.z, accA0.z); accA0.w = fmaf(a0, h00.w, accA0.w);
            accA1.x = fmaf(a0, h01.x, accA1.x); accA1.y = fmaf(a0, h01.y, accA1.y);
            accA1.z = fmaf(a0, h01.z, accA1.z); accA1.w = fmaf(a0, h01.w, accA1.w);
            accB0.x = fmaf(a1, h10.x, accB0.x); accB0.y = fmaf(a1, h10.y, accB0.y);
            accB0.z = fmaf(a1, h10.z, accB0.z); accB0.w = fmaf(a1, h10.w, accB0.w);
            accB1.x = fmaf(a1, h11.x, accB1.x); accB1.y = fmaf(a1, h11.y, accB1.y);
            accB1.z = fmaf(a1, h11.z, accB1.z); accB1.w = fmaf(a1, h11.w, accB1.w);
        }
        if (j < m) {
            int q0 = __shfl_sync(0xffffffffu, prt, j);
            int r0 = q0 & 0xFFFF, t0 = q0 >> 16;
            float s0 = __ldg(g_hl + r0 * NHEAD + head) + hrv + s_he[t0 * NHEAD + head];
            s0 = s0 > 0.f ? s0 : NEG * s0;
            float a0 = __expf(s0);
            dsum += a0;
            const float4* hp0 = (const float4*)(g_h + (size_t)r0 * NH + lane * 8);
            float4 h00 = __ldg(hp0), h01 = __ldg(hp0 + 1);
            accA0.x = fmaf(a0, h00.x, accA0.x); accA0.y = fmaf(a0, h00.y, accA0.y);
            accA0.z = fmaf(a0, h00.z, accA0.z); accA0.w = fmaf(a0, h00.w, accA0.w);
            accA1.x = fmaf(a0, h01.x, accA1.x); accA1.y = fmaf(a0, h01.y, accA1.y);
            accA1.z = fmaf(a0, h01.z, accA1.z); accA1.w = fmaf(a0, h01.w, accA1.w);
        }
    }

    float inv = (cnt > 0) ? (1.f / dsum) : 0.f;
    if ((lane & 3) == 0) g_denom[n * NHEAD + head] = (cnt > 0) ? dsum : 1.f;
    float4 o0, o1;
    o0.x = (accA0.x + accB0.x) * inv; o0.y = (accA0.y + accB0.y) * inv;
    o0.z = (accA0.z + accB0.z) * inv; o0.w = (accA0.w + accB0.w) * inv;
    o1.x = (accA1.x + accB1.x) * inv; o1.y = (accA1.y + accB1.y) * inv;
    o1.z = (accA1.z + accB1.z) * inv; o1.w = (accA1.w + accB1.w) * inv;
    float* op = out + (size_t)n * NH + lane * 8;
    *(float4*)op = o0;
    *(float4*)(op + 4) = o1;
}

// ------- attn output: recompute ex, divide by denom (after k_agg) ----------------
__global__ void k_norm(const int* __restrict__ row, const int* __restrict__ col,
                       const int* __restrict__ et, float* __restrict__ attn_out) {
    int e = blockIdx.x * blockDim.x + threadIdx.x;
    if (e >= N_EDGES) return;
    int rr = row[e], cc = col[e], tt = et[e];
    const float4* hl4 = (const float4*)(g_hl + rr * NHEAD);
    const float4* hr4 = (const float4*)(g_hr + cc * NHEAD);
    const float4* he4 = (const float4*)(g_he + tt * NHEAD);
    const float4* d4  = (const float4*)(g_denom + cc * NHEAD);
    float v[8];
#pragma unroll
    for (int q = 0; q < 2; q++) {
        float4 a = hl4[q], b = hr4[q], c = he4[q], d = d4[q];
        float s;
        s = a.x + b.x + c.x; s = s > 0.f ? s : NEG * s; v[q * 4 + 0] = __expf(s) / d.x;
        s = a.y + b.y + c.y; s = s > 0.f ? s : NEG * s; v[q * 4 + 1] = __expf(s) / d.y;
        s = a.z + b.z + c.z; s = s > 0.f ? s : NEG * s; v[q * 4 + 2] = __expf(s) / d.z;
        s = a.w + b.w + c.w; s = s > 0.f ? s : NEG * s; v[q * 4 + 3] = __expf(s) / d.w;
    }
    *(float4*)(attn_out + (size_t)e * 8 + 0) = make_float4(v[0], v[1], v[2], v[3]);
    *(float4*)(attn_out + (size_t)e * 8 + 4) = make_float4(v[4], v[5], v[6], v[7]);
}

// ---------------- launch ----------------
extern "C" void kernel_launch(void* const* d_in, const int* in_sizes, int n_in,
                              void* d_out, int out_size) {
    const float* x   = (const float*)d_in[0];
    const float* W   = (const float*)d_in[1];
    const float* We  = (const float*)d_in[2];
    const float* emb = (const float*)d_in[3];
    const float* a_l = (const float*)d_in[4];
    const float* a_r = (const float*)d_in[5];
    const float* a_e = (const float*)d_in[6];
    const int* row = (const int*)d_in[7];
    const int* col = (const int*)d_in[8];
    const int* et  = (const int*)d_in[9];
    float* out = (float*)d_out;
    float* attn_out = (out_size >= N_NODES * NH + N_EDGES * NHEAD)
                          ? (out + (size_t)N_NODES * NH)
                          : nullptr;

    const int EB = (N_EDGES + 255) / 256;

    k_init<<<(N_NODES + 255) / 256, 256>>>(emb, We, a_e);
    k_wsplit<<<(D_IN * NH + 255) / 256, 256>>>(W);

    dim3 ggrid(2, (N_NODES + 127) / 128);
    k_gemm_tc<<<ggrid, 256>>>(x, a_l, a_r);

    k_hist<<<EB, 256>>>(col);
    k_scanA<<<NB, 256>>>();
    k_scanB<<<1, 256>>>();
    k_scanC<<<NB, 256>>>();
    k_scatter<<<EB, 256>>>(row, col, et);

    k_agg<<<(N_NODES + 7) / 8, 256>>>(out);
    if (attn_out) k_norm<<<EB, 256>>>(row, col, et, attn_out);
}

// round 10
// speedup vs baseline: 1.6487x; 1.0050x over previous
#include <cuda_runtime.h>
#include <math.h>

#define N_NODES 50000
#define N_EDGES 800000
#define NHEAD 8
#define D_OUT 32
#define D_IN 256
#define NH 256            // NHEAD * D_OUT
#define E_FEAT 64
#define N_ETYPES 5
#define NEG 0.2f
#define NB 196            // ceil(N_NODES / 256)

// ---------------- scratch (device globals; no allocation allowed) ----------------
__device__ float    g_h[N_NODES * NH];          // projected node features [N,8,32]
__device__ float    g_hl[N_NODES * NHEAD];
__device__ float    g_hr[N_NODES * NHEAD];
__device__ float    g_he[N_ETYPES * NHEAD];
__device__ float    g_denom[N_NODES * NHEAD];   // written by k_agg (no atomics)
__device__ int      g_counts[N_NODES];
__device__ int      g_offs[N_NODES];
__device__ int      g_cursor[N_NODES];
__device__ int      g_rt[N_EDGES];              // CSR order: row | (etype<<16)
__device__ int      g_bsums[256];
__device__ uint2    g_Wsp[D_IN * NH];           // W pre-split into tf32 (hi, lo)

// ---------------- tf32 helpers ----------------
__device__ __forceinline__ unsigned cvt_tf32(float x) {
    unsigned r;
    asm("cvt.rna.tf32.f32 %0, %1;" : "=r"(r) : "f"(x));
    return r;
}
__device__ __forceinline__ void tf32_split(float x, unsigned& hi, unsigned& lo) {
    hi = cvt_tf32(x);
    lo = cvt_tf32(x - __uint_as_float(hi));
}
__device__ __forceinline__ void mma_tf32(float* d, const unsigned* a, const unsigned* b) {
    asm volatile(
        "mma.sync.aligned.m16n8k8.row.col.f32.tf32.tf32.f32 "
        "{%0,%1,%2,%3}, {%4,%5,%6,%7}, {%8,%9}, {%0,%1,%2,%3};"
        : "+f"(d[0]), "+f"(d[1]), "+f"(d[2]), "+f"(d[3])
        : "r"(a[0]), "r"(a[1]), "r"(a[2]), "r"(a[3]), "r"(b[0]), "r"(b[1]));
}

// ---------------- init (+ fused he: per-etype attention dots) ----------------
__global__ void k_init(const float* __restrict__ emb, const float* __restrict__ We,
                       const float* __restrict__ a_e) {
    int i = blockIdx.x * blockDim.x + threadIdx.x;
    if (i < N_NODES) g_counts[i] = 0;
    if (blockIdx.x < N_ETYPES * NHEAD) {
        int t = blockIdx.x >> 3, hd = blockIdx.x & 7;
        __shared__ float r2[2];
        float s = 0.f;
        if (threadIdx.x < 64) {
            int f = threadIdx.x;
            float ev = 0.f;
#pragma unroll 8
            for (int k = 0; k < E_FEAT; k++)
                ev += emb[t * E_FEAT + k] * We[k * (E_FEAT * NHEAD) + hd * E_FEAT + f];
            s = ev * a_e[hd * E_FEAT + f];
#pragma unroll
            for (int o = 16; o >= 1; o >>= 1) s += __shfl_xor_sync(0xffffffffu, s, o);
            if ((threadIdx.x & 31) == 0) r2[threadIdx.x >> 5] = s;
        }
        __syncthreads();
        if (threadIdx.x == 0) g_he[t * NHEAD + hd] = r2[0] + r2[1];
    }
}

// ---------------- pre-split W into tf32 hi/lo ----------------
__global__ void k_wsplit(const float* __restrict__ W) {
    int i = blockIdx.x * blockDim.x + threadIdx.x;
    if (i < D_IN * NH) {
        unsigned hi, lo;
        tf32_split(W[i], hi, lo);
        g_Wsp[i] = make_uint2(hi, lo);
    }
}

// -------- GEMM: h = x @ W via 3xTF32 (smem X + pre-split W) + fused hl/hr ---------
__global__ __launch_bounds__(256, 2) void k_gemm_tc(const float* __restrict__ X,
                                                    const float* __restrict__ a_l,
                                                    const float* __restrict__ a_r) {
    __shared__ float Xs[8][136];
    int warp = threadIdx.x >> 5, lane = threadIdx.x & 31;
    int gid = lane >> 2, tig = lane & 3;
    int wm = (warp >> 1) * 32;
    int wn = (warp & 1) * 64;
    int m0 = blockIdx.y * 128;
    int n0 = blockIdx.x * 128;

    float acc[2][8][4];
#pragma unroll
    for (int mt = 0; mt < 2; mt++)
#pragma unroll
        for (int nt = 0; nt < 8; nt++)
#pragma unroll
            for (int c = 0; c < 4; c++) acc[mt][nt][c] = 0.f;

    int srow = threadIdx.x >> 1;
    int skq = (threadIdx.x & 1) * 4;
    bool srow_ok = (m0 + srow) < N_NODES;
    const float* xp = X + (size_t)(m0 + srow) * D_IN + skq;

    for (int k0 = 0; k0 < D_IN; k0 += 8) {
        float4 v = make_float4(0.f, 0.f, 0.f, 0.f);
        if (srow_ok) v = *(const float4*)(xp + k0);
        Xs[skq + 0][srow] = v.x;
        Xs[skq + 1][srow] = v.y;
        Xs[skq + 2][srow] = v.z;
        Xs[skq + 3][srow] = v.w;
        __syncthreads();

        unsigned ah[2][4], al[2][4];
#pragma unroll
        for (int mt = 0; mt < 2; mt++) {
            int r = wm + mt * 16 + gid;
            tf32_split(Xs[tig][r],         ah[mt][0], al[mt][0]);
            tf32_split(Xs[tig][r + 8],     ah[mt][1], al[mt][1]);
            tf32_split(Xs[tig + 4][r],     ah[mt][2], al[mt][2]);
            tf32_split(Xs[tig + 4][r + 8], ah[mt][3], al[mt][3]);
        }
#pragma unroll
        for (int nt = 0; nt < 8; nt++) {
            int c = n0 + wn + nt * 8 + gid;
            uint2 b0 = g_Wsp[(size_t)(k0 + tig) * NH + c];
            uint2 b1 = g_Wsp[(size_t)(k0 + tig + 4) * NH + c];
            unsigned bh[2] = {b0.x, b1.x};
            unsigned bl[2] = {b0.y, b1.y};
#pragma unroll
            for (int mt = 0; mt < 2; mt++) {
                mma_tf32(acc[mt][nt], ah[mt], bh);
                mma_tf32(acc[mt][nt], al[mt], bh);
                mma_tf32(acc[mt][nt], ah[mt], bl);
            }
        }
        __syncthreads();
    }

    // store h
#pragma unroll
    for (int mt = 0; mt < 2; mt++) {
        int r1 = m0 + wm + mt * 16 + gid;
        int r2 = r1 + 8;
#pragma unroll
        for (int nt = 0; nt < 8; nt++) {
            int c = n0 + wn + nt * 8 + 2 * tig;
            if (r1 < N_NODES)
                *(float2*)&g_h[(size_t)r1 * NH + c] = make_float2(acc[mt][nt][0], acc[mt][nt][1]);
            if (r2 < N_NODES)
                *(float2*)&g_h[(size_t)r2 * NH + c] = make_float2(acc[mt][nt][2], acc[mt][nt][3]);
        }
    }

    // fused hl/hr: this warp's 64 cols = heads headA, headA+1
    int headA = (n0 + wn) >> 5;
#pragma unroll
    for (int hh = 0; hh < 2; hh++) {
        int head = headA + hh;
#pragma unroll
        for (int mt = 0; mt < 2; mt++) {
            float l1 = 0.f, r1v = 0.f, l2 = 0.f, r2v = 0.f;
#pragma unroll
            for (int q = 0; q < 4; q++) {
                int nt = hh * 4 + q;
                int d = q * 8 + 2 * tig;
                float al0 = __ldg(a_l + head * D_OUT + d);
                float al1 = __ldg(a_l + head * D_OUT + d + 1);
                float ar0 = __ldg(a_r + head * D_OUT + d);
                float ar1 = __ldg(a_r + head * D_OUT + d + 1);
                l1  += acc[mt][nt][0] * al0 + acc[mt][nt][1] * al1;
                r1v += acc[mt][nt][0] * ar0 + acc[mt][nt][1] * ar1;
                l2  += acc[mt][nt][2] * al0 + acc[mt][nt][3] * al1;
                r2v += acc[mt][nt][2] * ar0 + acc[mt][nt][3] * ar1;
            }
#pragma unroll
            for (int o = 1; o <= 2; o <<= 1) {
                l1  += __shfl_xor_sync(0xffffffffu, l1, o);
                r1v += __shfl_xor_sync(0xffffffffu, r1v, o);
                l2  += __shfl_xor_sync(0xffffffffu, l2, o);
                r2v += __shfl_xor_sync(0xffffffffu, r2v, o);
            }
            if (tig == 0) {
                int rr1 = m0 + wm + mt * 16 + gid;
                int rr2 = rr1 + 8;
                if (rr1 < N_NODES) { g_hl[rr1 * NHEAD + head] = l1; g_hr[rr1 * NHEAD + head] = r1v; }
                if (rr2 < N_NODES) { g_hl[rr2 * NHEAD + head] = l2; g_hr[rr2 * NHEAD + head] = r2v; }
            }
        }
    }
}

// ---------------- histogram over col ----------------
__global__ void k_hist(const int* __restrict__ col) {
    int e = blockIdx.x * blockDim.x + threadIdx.x;
    if (e < N_EDGES) atomicAdd(&g_counts[col[e]], 1);
}

// ---------------- scans (CSR offsets over col histogram) ----------------
__global__ void k_scanA() {
    int i = blockIdx.x * 256 + threadIdx.x;
    int v = (i < N_NODES) ? g_counts[i] : 0;
    int x = v;
    int lane = threadIdx.x & 31, wid = threadIdx.x >> 5;
#pragma unroll
    for (int o = 1; o < 32; o <<= 1) {
        int y = __shfl_up_sync(0xffffffffu, x, o);
        if (lane >= o) x += y;
    }
    __shared__ int ws[8];
    if (lane == 31) ws[wid] = x;
    __syncthreads();
    if (threadIdx.x == 0) {
        int s = 0;
        for (int w = 0; w < 8; w++) { int t = ws[w]; ws[w] = s; s += t; }
    }
    __syncthreads();
    int excl = x - v + ws[wid];
    if (i < N_NODES) g_offs[i] = excl;
    if (threadIdx.x == 255) g_bsums[blockIdx.x] = excl + v;
}

__global__ void k_scanB() {
    int i = threadIdx.x;
    int v = (i < NB) ? g_bsums[i] : 0;
    int x = v;
    int lane = threadIdx.x & 31, wid = threadIdx.x >> 5;
#pragma unroll
    for (int o = 1; o < 32; o <<= 1) {
        int y = __shfl_up_sync(0xffffffffu, x, o);
        if (lane >= o) x += y;
    }
    __shared__ int ws[8];
    if (lane == 31) ws[wid] = x;
    __syncthreads();
    if (threadIdx.x == 0) {
        int s = 0;
        for (int w = 0; w < 8; w++) { int t = ws[w]; ws[w] = s; s += t; }
    }
    __syncthreads();
    int excl = x - v + ws[wid];
    if (i < NB) g_bsums[i] = excl;
}

__global__ void k_scanC() {
    int i = blockIdx.x * 256 + threadIdx.x;
    if (i < N_NODES) {
        int o = g_offs[i] + g_bsums[blockIdx.x];
        g_offs[i] = o;
        g_cursor[i] = o;
    }
}

// ---------------- CSR scatter: pack (row, etype) per position ----------------
__global__ void k_scatter(const int* __restrict__ row, const int* __restrict__ col,
                          const int* __restrict__ et) {
    int e = blockIdx.x * blockDim.x + threadIdx.x;
    if (e >= N_EDGES) return;
    int cc = col[e];
    int pos = atomicAdd(&g_cursor[cc], 1);
    g_rt[pos] = row[e] | (et[e] << 16);
}

// ------- CSR aggregation: warp per node; recomputes ex inline; owns denom ----------
__global__ __launch_bounds__(256) void k_agg(float* __restrict__ out) {
    __shared__ float s_he[N_ETYPES * NHEAD];
    if (threadIdx.x < N_ETYPES * NHEAD) s_he[threadIdx.x] = g_he[threadIdx.x];
    __syncthreads();

    int n = blockIdx.x * 8 + (threadIdx.x >> 5);
    if (n >= N_NODES) return;
    int lane = threadIdx.x & 31;
    int head = lane >> 2;               // 8 dims per lane -> head = lane/4
    int start = g_offs[n];
    int cnt = g_counts[n];
    float hrv = g_hr[n * NHEAD + head];   // warp-constant per head group

    float4 accA0 = make_float4(0.f, 0.f, 0.f, 0.f), accA1 = accA0;
    float4 accB0 = accA0, accB1 = accA0;
    float dsum = 0.f;

    for (int base = 0; base < cnt; base += 32) {
        int m = min(cnt - base, 32);
        int prt = 0;
        if (lane < m) prt = g_rt[start + base + lane];
        int j = 0;
        for (; j + 2 <= m; j += 2) {
            int q0 = __shfl_sync(0xffffffffu, prt, j);
            int q1 = __shfl_sync(0xffffffffu, prt, j + 1);
            int r0 = q0 & 0xFFFF, t0 = q0 >> 16;
            int r1 = q1 & 0xFFFF, t1 = q1 >> 16;
            float s0 = __ldg(g_hl + r0 * NHEAD + head) + hrv + s_he[t0 * NHEAD + head];
            float s1 = __ldg(g_hl + r1 * NHEAD + head) + hrv + s_he[t1 * NHEAD + head];
            s0 = s0 > 0.f ? s0 : NEG * s0;
            s1 = s1 > 0.f ? s1 : NEG * s1;
            float a0 = __expf(s0), a1 = __expf(s1);
            dsum += a0 + a1;
            const float4* hp0 = (const float4*)(g_h + (size_t)r0 * NH + lane * 8);
            const float4* hp1 = (const float4*)(g_h + (size_t)r1 * NH + lane * 8);
            float4 h00 = __ldg(hp0), h01 = __ldg(hp0 + 1);
            float4 h10 = __ldg(hp1), h11 = __ldg(hp1 + 1);
            accA0.x = fmaf(a0, h00.x, accA0.x); accA0.y = fmaf(a0, h00.y, accA0.y);
            accA0.z = fmaf(a0, h00.z, accA0.z); accA0.w = fmaf(a0, h00.w, accA0.w);
            accA1.x = fmaf(a0, h01.x, accA1.x); accA1.y = fmaf(a0, h01.y, accA1.y);
            accA1.z = fmaf(a0, h01.z, accA1.z); accA1.w = fmaf(a0, h01.w, accA1.w);
            accB0.x = fmaf(a1, h10.x, accB0.x); accB0.y = fmaf(a1, h10.y, accB0.y);
            accB0.z = fmaf(a1, h10.z, accB0.z); accB0.w = fmaf(a1, h10.w, accB0.w);
            accB1.x = fmaf(a1, h11.x, accB1.x); accB1.y = fmaf(a1, h11.y, accB1.y);
            accB1.z = fmaf(a1, h11.z, accB1.z); accB1.w = fmaf(a1, h11.w, accB1.w);
        }
        if (j < m) {
            int q0 = __shfl_sync(0xffffffffu, prt, j);
            int r0 = q0 & 0xFFFF, t0 = q0 >> 16;
            float s0 = __ldg(g_hl + r0 * NHEAD + head) + hrv + s_he[t0 * NHEAD + head];
            s0 = s0 > 0.f ? s0 : NEG * s0;
            float a0 = __expf(s0);
            dsum += a0;
            const float4* hp0 = (const float4*)(g_h + (size_t)r0 * NH + lane * 8);
            float4 h00 = __ldg(hp0), h01 = __ldg(hp0 + 1);
            accA0.x = fmaf(a0, h00.x, accA0.x); accA0.y = fmaf(a0, h00.y, accA0.y);
            accA0.z = fmaf(a0, h00.z, accA0.z); accA0.w = fmaf(a0, h00.w, accA0.w);
            accA1.x = fmaf(a0, h01.x, accA1.x); accA1.y = fmaf(a0, h01.y, accA1.y);
            accA1.z = fmaf(a0, h01.z, accA1.z); accA1.w = fmaf(a0, h01.w, accA1.w);
        }
    }

    float inv = (cnt > 0) ? (1.f / dsum) : 0.f;
    if ((lane & 3) == 0) g_denom[n * NHEAD + head] = (cnt > 0) ? dsum : 1.f;
    float4 o0, o1;
    o0.x = (accA0.x + accB0.x) * inv; o0.y = (accA0.y + accB0.y) * inv;
    o0.z = (accA0.z + accB0.z) * inv; o0.w = (accA0.w + accB0.w) * inv;
    o1.x = (accA1.x + accB1.x) * inv; o1.y = (accA1.y + accB1.y) * inv;
    o1.z = (accA1.z + accB1.z) * inv; o1.w = (accA1.w + accB1.w) * inv;
    float* op = out + (size_t)n * NH + lane * 8;
    *(float4*)op = o0;
    *(float4*)(op + 4) = o1;
}

// ------- attn output: recompute ex, divide by denom (after k_agg) ----------------
__global__ void k_norm(const int* __restrict__ row, const int* __restrict__ col,
                       const int* __restrict__ et, float* __restrict__ attn_out) {
    int e = blockIdx.x * blockDim.x + threadIdx.x;
    if (e >= N_EDGES) return;
    int rr = row[e], cc = col[e], tt = et[e];
    const float4* hl4 = (const float4*)(g_hl + rr * NHEAD);
    const float4* hr4 = (const float4*)(g_hr + cc * NHEAD);
    const float4* he4 = (const float4*)(g_he + tt * NHEAD);
    const float4* d4  = (const float4*)(g_denom + cc * NHEAD);
    float v[8];
#pragma unroll
    for (int q = 0; q < 2; q++) {
        float4 a = hl4[q], b = hr4[q], c = he4[q], d = d4[q];
        float s;
        s = a.x + b.x + c.x; s = s > 0.f ? s : NEG * s; v[q * 4 + 0] = __expf(s) / d.x;
        s = a.y + b.y + c.y; s = s > 0.f ? s : NEG * s; v[q * 4 + 1] = __expf(s) / d.y;
        s = a.z + b.z + c.z; s = s > 0.f ? s : NEG * s; v[q * 4 + 2] = __expf(s) / d.z;
        s = a.w + b.w + c.w; s = s > 0.f ? s : NEG * s; v[q * 4 + 3] = __expf(s) / d.w;
    }
    *(float4*)(attn_out + (size_t)e * 8 + 0) = make_float4(v[0], v[1], v[2], v[3]);
    *(float4*)(attn_out + (size_t)e * 8 + 4) = make_float4(v[4], v[5], v[6], v[7]);
}

// ---------------- launch ----------------
extern "C" void kernel_launch(void* const* d_in, const int* in_sizes, int n_in,
                              void* d_out, int out_size) {
    const float* x   = (const float*)d_in[0];
    const float* W   = (const float*)d_in[1];
    const float* We  = (const float*)d_in[2];
    const float* emb = (const float*)d_in[3];
    const float* a_l = (const float*)d_in[4];
    const float* a_r = (const float*)d_in[5];
    const float* a_e = (const float*)d_in[6];
    const int* row = (const int*)d_in[7];
    const int* col = (const int*)d_in[8];
    const int* et  = (const int*)d_in[9];
    float* out = (float*)d_out;
    float* attn_out = (out_size >= N_NODES * NH + N_EDGES * NHEAD)
                          ? (out + (size_t)N_NODES * NH)
                          : nullptr;

    const int EB = (N_EDGES + 255) / 256;

    k_init<<<(N_NODES + 255) / 256, 256>>>(emb, We, a_e);
    k_wsplit<<<(D_IN * NH + 255) / 256, 256>>>(W);

    dim3 ggrid(2, (N_NODES + 127) / 128);
    k_gemm_tc<<<ggrid, 256>>>(x, a_l, a_r);

    k_hist<<<EB, 256>>>(col);
    k_scanA<<<NB, 256>>>();
    k_scanB<<<1, 256>>>();
    k_scanC<<<NB, 256>>>();
    k_scatter<<<EB, 256>>>(row, col, et);

    k_agg<<<(N_NODES + 7) / 8, 256>>>(out);
    if (attn_out) k_norm<<<EB, 256>>>(row, col, et, attn_out);
}